// round 14
// baseline (speedup 1.0000x reference)
#include <cuda_runtime.h>
#include <cuda_pipeline.h>
#include <cuda_bf16.h>
#include <cuda_fp16.h>
#include <math.h>
#include <stdint.h>

// ---------------- problem dims ----------------
#define T_LEN   512
#define BSZ     8
#define M_TOT   (T_LEN * BSZ)      // 4096
#define M_HALF  (M_TOT / 2)        // 2048
#define T_HALF  (T_LEN / 2)        // 256
#define OBS_DIM 256
#define D_IN    2048
#define NHEAD   16
#define NSTATE  64
#define PHEAD   128
#define NUNITS  256
#define NACT    64
#define HN      (NHEAD * NSTATE)    // 1024
#define WSCALE  32.0f
#define WISCALE (1.0f / 32.0f)

// ---------------- scratch ----------------
__device__ float          g_X   [M_TOT * D_IN];
__device__ __half         g_Xh  [M_TOT * D_IN];
__device__ float          g_Bm  [M_TOT * HN];
__device__ float          g_Cm  [M_TOT * HN];
__device__ float          g_dt  [M_TOT * NHEAD];
__device__ float          g_dec [M_TOT * NHEAD];
__device__ __half         g_Yh  [M_TOT * D_IN];          // final fp16 Y
__device__ float          g_Yu  [M_HALF * D_IN];         // seg1 uncorrected y (fp32)
__device__ float          g_Zp  [2 * M_TOT * NUNITS];
__device__ unsigned long long g_hstate[128 * 128 * 32];  // H_mid (packed f32x2)
__device__ __nv_bfloat16  g_obs_hi[M_TOT * OBS_DIM];
__device__ __nv_bfloat16  g_obs_lo[M_TOT * OBS_DIM];
__device__ __nv_bfloat16  g_Win_hi[D_IN * OBS_DIM];
__device__ __nv_bfloat16  g_Win_lo[D_IN * OBS_DIM];
__device__ __half         g_WB_h [HN * D_IN];
__device__ __half         g_WC_h [HN * D_IN];
__device__ __half         g_Wyo_h[NUNITS * D_IN];

// ---------------- helpers ----------------
__device__ __forceinline__ uint32_t smem_u32(const void* p) {
    uint32_t a;
    asm("{ .reg .u64 t; cvta.to.shared.u64 t, %1; cvt.u32.u64 %0, t; }" : "=r"(a) : "l"(p));
    return a;
}
__device__ __forceinline__ void ldsm_x4(uint32_t* r, uint32_t addr) {
    asm volatile("ldmatrix.sync.aligned.m8n8.x4.shared.b16 {%0,%1,%2,%3}, [%4];"
                 : "=r"(r[0]), "=r"(r[1]), "=r"(r[2]), "=r"(r[3]) : "r"(addr));
}
__device__ __forceinline__ void ldsm_x2(uint32_t* r, uint32_t addr) {
    asm volatile("ldmatrix.sync.aligned.m8n8.x2.shared.b16 {%0,%1}, [%2];"
                 : "=r"(r[0]), "=r"(r[1]) : "r"(addr));
}
__device__ __forceinline__ void mma_bf16(float* c, const uint32_t* a, const uint32_t* b) {
    asm volatile("mma.sync.aligned.m16n8k16.row.col.f32.bf16.bf16.f32 "
                 "{%0,%1,%2,%3}, {%4,%5,%6,%7}, {%8,%9}, {%0,%1,%2,%3};"
                 : "+f"(c[0]), "+f"(c[1]), "+f"(c[2]), "+f"(c[3])
                 : "r"(a[0]), "r"(a[1]), "r"(a[2]), "r"(a[3]), "r"(b[0]), "r"(b[1]));
}
__device__ __forceinline__ void mma_f16(float* c, const uint32_t* a, const uint32_t* b) {
    asm volatile("mma.sync.aligned.m16n8k16.row.col.f32.f16.f16.f32 "
                 "{%0,%1,%2,%3}, {%4,%5,%6,%7}, {%8,%9}, {%0,%1,%2,%3};"
                 : "+f"(c[0]), "+f"(c[1]), "+f"(c[2]), "+f"(c[3])
                 : "r"(a[0]), "r"(a[1]), "r"(a[2]), "r"(a[3]), "r"(b[0]), "r"(b[1]));
}
typedef unsigned long long ull;
__device__ __forceinline__ ull pk2(float lo, float hi) {
    ull r; asm("mov.b64 %0, {%1, %2};" : "=l"(r) : "f"(lo), "f"(hi)); return r;
}
__device__ __forceinline__ void upk2(float& lo, float& hi, ull v) {
    asm("mov.b64 {%0, %1}, %2;" : "=f"(lo), "=f"(hi) : "l"(v));
}
__device__ __forceinline__ ull fma2(ull a, ull b, ull c) {
    ull d; asm("fma.rn.f32x2 %0, %1, %2, %3;" : "=l"(d) : "l"(a), "l"(b), "l"(c)); return d;
}
__device__ __forceinline__ ull mul2(ull a, ull b) {
    ull d; asm("mul.rn.f32x2 %0, %1, %2;" : "=l"(d) : "l"(a), "l"(b)); return d;
}

// ---------------- conversion kernels ----------------
__global__ void rowconv_kernel(const float* __restrict__ src,
                               __nv_bfloat16* __restrict__ hi,
                               __nv_bfloat16* __restrict__ lo, int n)
{
    int i = blockIdx.x * blockDim.x + threadIdx.x;
    if (i * 4 >= n) return;
    float4 v = *(const float4*)(src + i * 4);
    float vv[4] = {v.x, v.y, v.z, v.w};
#pragma unroll
    for (int j = 0; j < 4; j++) {
        __nv_bfloat16 h = __float2bfloat16(vv[j]);
        hi[i * 4 + j] = h;
        lo[i * 4 + j] = __float2bfloat16(vv[j] - __bfloat162float(h));
    }
}

__global__ void transconv_kernel(const float* __restrict__ W,
                                 __nv_bfloat16* __restrict__ Thi,
                                 __nv_bfloat16* __restrict__ Tlo, int K, int N)
{
    __shared__ float s[32][33];
    int tx = threadIdx.x, ty = threadIdx.y;
    int n0 = blockIdx.x * 32, k0 = blockIdx.y * 32;
#pragma unroll
    for (int i = 0; i < 4; i++)
        s[ty + i * 8][tx] = W[(size_t)(k0 + ty + i * 8) * N + n0 + tx];
    __syncthreads();
#pragma unroll
    for (int i = 0; i < 4; i++) {
        int n = n0 + ty + i * 8, k = k0 + tx;
        float v = s[tx][ty + i * 8];
        __nv_bfloat16 h = __float2bfloat16(v);
        Thi[(size_t)n * K + k] = h;
        Tlo[(size_t)n * K + k] = __float2bfloat16(v - __bfloat162float(h));
    }
}

__global__ void transconv_h_kernel(const float* __restrict__ W,
                                   __half* __restrict__ Th, int K, int N)
{
    __shared__ float s[32][33];
    int tx = threadIdx.x, ty = threadIdx.y;
    int n0 = blockIdx.x * 32, k0 = blockIdx.y * 32;
#pragma unroll
    for (int i = 0; i < 4; i++)
        s[ty + i * 8][tx] = W[(size_t)(k0 + ty + i * 8) * N + n0 + tx];
    __syncthreads();
#pragma unroll
    for (int i = 0; i < 4; i++) {
        int n = n0 + ty + i * 8, k = k0 + tx;
        Th[(size_t)n * K + k] = __float2half_rn(s[tx][ty + i * 8] * WSCALE);
    }
}

// ---------------- tile geometry ----------------
#define ROWB      80
#define TILE_B    (128 * ROWB)
#define BUF_B4    (4 * TILE_B)
#define SMEM_BF16 (2 * BUF_B4)
#define BUF_B2    (2 * TILE_B)
#define SMEM_F16_2 (2 * BUF_B2)

// ---------------- bf16x3 GEMM (GEMM1) ----------------
template<int KCHUNKS>
__global__ __launch_bounds__(256, 2)
void mma_gemm_bf3(const __nv_bfloat16* __restrict__ Ahi, const __nv_bfloat16* __restrict__ Alo,
                  const __nv_bfloat16* __restrict__ Bhi, const __nv_bfloat16* __restrict__ Blo,
                  const float* __restrict__ bias,
                  float* __restrict__ Cout, __half* __restrict__ Ch,
                  int M, int N, int K)
{
    extern __shared__ char smem[];
    const uint32_t sbase = smem_u32(smem);
    const int tid  = threadIdx.x;
    const int lane = tid & 31, wid = tid >> 5;
    const int warp_m = wid >> 2;
    const int warp_n = wid & 3;
    const int bn = blockIdx.x * 128;
    const int bm = blockIdx.y * 128;

    const __nv_bfloat16* srcs[4] = {Ahi, Alo, Bhi, Blo};

    auto load_chunk = [&](int c, int buf) {
#pragma unroll
        for (int w = 0; w < 4; w++) {
            const int rowbase = (w < 2) ? bm : bn;
            const __nv_bfloat16* src = srcs[w];
#pragma unroll
            for (int t = 0; t < 2; t++) {
                int idx = tid + t * 256;
                int row = idx >> 2, seg = idx & 3;
                char* dst = smem + buf * BUF_B4 + w * TILE_B + row * ROWB + seg * 16;
                const char* s = (const char*)src +
                    ((size_t)(rowbase + row) * K + (size_t)c * 32) * 2 + seg * 16;
                __pipeline_memcpy_async(dst, s, 16);
            }
        }
    };

    float acc[4][4][4];
#pragma unroll
    for (int i = 0; i < 4; i++)
#pragma unroll
        for (int j = 0; j < 4; j++)
#pragma unroll
            for (int q = 0; q < 4; q++) acc[i][j][q] = 0.f;

    load_chunk(0, 0);
    __pipeline_commit();
    __pipeline_wait_prior(0);
    __syncthreads();

    const uint32_t a_lane_off = (uint32_t)((lane & 15) * ROWB + (lane >> 4) * 16);
    const uint32_t b_lane_off = (uint32_t)((lane & 7) * ROWB + ((lane >> 3) & 1) * 16);

    for (int c = 0; c < KCHUNKS; c++) {
        if (c + 1 < KCHUNKS) { load_chunk(c + 1, (c + 1) & 1); __pipeline_commit(); }
        const uint32_t bufb = sbase + (c & 1) * BUF_B4;
#pragma unroll
        for (int s = 0; s < 2; s++) {
            uint32_t ah[4][4], al[4][4];
            const uint32_t ks = s * 32;
#pragma unroll
            for (int i = 0; i < 4; i++) {
                uint32_t ro = (uint32_t)((warp_m * 64 + i * 16) * ROWB) + ks + a_lane_off;
                ldsm_x4(ah[i], bufb + 0 * TILE_B + ro);
                ldsm_x4(al[i], bufb + 1 * TILE_B + ro);
            }
#pragma unroll
            for (int j = 0; j < 4; j++) {
                uint32_t bh[2], bl[2];
                uint32_t ro = (uint32_t)((warp_n * 32 + j * 8) * ROWB) + ks + b_lane_off;
                ldsm_x2(bh, bufb + 2 * TILE_B + ro);
                ldsm_x2(bl, bufb + 3 * TILE_B + ro);
#pragma unroll
                for (int i = 0; i < 4; i++) {
                    mma_bf16(acc[i][j], ah[i], bh);
                    mma_bf16(acc[i][j], ah[i], bl);
                    mma_bf16(acc[i][j], al[i], bh);
                }
            }
        }
        if (c + 1 < KCHUNKS) __pipeline_wait_prior(0);
        __syncthreads();
    }

    const int r0 = lane >> 2;
    const int q0 = (lane & 3) * 2;
#pragma unroll
    for (int j = 0; j < 4; j++) {
        const int n0 = bn + warp_n * 32 + j * 8 + q0;
        float b0 = bias[n0], b1 = bias[n0 + 1];
#pragma unroll
        for (int i = 0; i < 4; i++) {
            const int m0 = bm + warp_m * 64 + i * 16 + r0;
            float v0 = fmaxf(acc[i][j][0] + b0, 0.f);
            float v1 = fmaxf(acc[i][j][1] + b1, 0.f);
            float v2 = fmaxf(acc[i][j][2] + b0, 0.f);
            float v3 = fmaxf(acc[i][j][3] + b1, 0.f);
            *(float2*)&Cout[(size_t)m0 * N + n0]       = make_float2(v0, v1);
            *(float2*)&Cout[(size_t)(m0 + 8) * N + n0] = make_float2(v2, v3);
            __half2 hp0 = {__float2half_rn(v0), __float2half_rn(v1)};
            __half2 hp1 = {__float2half_rn(v2), __float2half_rn(v3)};
            *(__half2*)&Ch[(size_t)m0 * N + n0]       = hp0;
            *(__half2*)&Ch[(size_t)(m0 + 8) * N + n0] = hp1;
        }
    }
}

// ---------------- fp16 single-pass GEMM (B, C, yo) -------------------------
template<int KCHUNKS>
__global__ __launch_bounds__(256, 2)
void mma_gemm_h1(const __half* __restrict__ A, const __half* __restrict__ Wm,
                 float* __restrict__ Cout, int M, int N, int K, size_t zstride)
{
    extern __shared__ char smem[];
    const uint32_t sbase = smem_u32(smem);
    const int tid  = threadIdx.x;
    const int lane = tid & 31, wid = tid >> 5;
    const int warp_m = wid >> 2;
    const int warp_n = wid & 3;
    const int bn = blockIdx.x * 128;
    const int bm = blockIdx.y * 128;
    const int zoff = blockIdx.z * KCHUNKS;
    Cout += (size_t)blockIdx.z * zstride;

    const __half* srcs[2] = {A, Wm};

    auto load_chunk = [&](int gc, int buf) {
#pragma unroll
        for (int w = 0; w < 2; w++) {
            const int rowbase = (w == 0) ? bm : bn;
            const __half* src = srcs[w];
#pragma unroll
            for (int t = 0; t < 2; t++) {
                int idx = tid + t * 256;
                int row = idx >> 2, seg = idx & 3;
                char* dst = smem + buf * BUF_B2 + w * TILE_B + row * ROWB + seg * 16;
                const char* s = (const char*)src +
                    ((size_t)(rowbase + row) * K + (size_t)gc * 32) * 2 + seg * 16;
                __pipeline_memcpy_async(dst, s, 16);
            }
        }
    };

    float acc[4][4][4];
#pragma unroll
    for (int i = 0; i < 4; i++)
#pragma unroll
        for (int j = 0; j < 4; j++)
#pragma unroll
            for (int q = 0; q < 4; q++) acc[i][j][q] = 0.f;

    load_chunk(zoff, 0);
    __pipeline_commit();
    __pipeline_wait_prior(0);
    __syncthreads();

    const uint32_t a_lane_off = (uint32_t)((lane & 15) * ROWB + (lane >> 4) * 16);
    const uint32_t b_lane_off = (uint32_t)((lane & 7) * ROWB + ((lane >> 3) & 1) * 16);

    for (int c = 0; c < KCHUNKS; c++) {
        if (c + 1 < KCHUNKS) { load_chunk(zoff + c + 1, (c + 1) & 1); __pipeline_commit(); }
        const uint32_t bufb = sbase + (c & 1) * BUF_B2;
#pragma unroll
        for (int s = 0; s < 2; s++) {
            uint32_t af[4][4];
            const uint32_t ks = s * 32;
#pragma unroll
            for (int i = 0; i < 4; i++) {
                uint32_t ro = (uint32_t)((warp_m * 64 + i * 16) * ROWB) + ks + a_lane_off;
                ldsm_x4(af[i], bufb + 0 * TILE_B + ro);
            }
#pragma unroll
            for (int j = 0; j < 4; j++) {
                uint32_t wf[2];
                uint32_t ro = (uint32_t)((warp_n * 32 + j * 8) * ROWB) + ks + b_lane_off;
                ldsm_x2(wf, bufb + 1 * TILE_B + ro);
#pragma unroll
                for (int i = 0; i < 4; i++)
                    mma_f16(acc[i][j], af[i], wf);
            }
        }
        if (c + 1 < KCHUNKS) __pipeline_wait_prior(0);
        __syncthreads();
    }

    const int r0 = lane >> 2;
    const int q0 = (lane & 3) * 2;
#pragma unroll
    for (int j = 0; j < 4; j++) {
        const int n0 = bn + warp_n * 32 + j * 8 + q0;
#pragma unroll
        for (int i = 0; i < 4; i++) {
            const int m0 = bm + warp_m * 64 + i * 16 + r0;
            *(float2*)&Cout[(size_t)m0 * N + n0] =
                make_float2(acc[i][j][0] * WISCALE, acc[i][j][1] * WISCALE);
            *(float2*)&Cout[(size_t)(m0 + 8) * N + n0] =
                make_float2(acc[i][j][2] * WISCALE, acc[i][j][3] * WISCALE);
        }
    }
}

// ---------------- dt projection + softplus + decay ----------------
__global__ __launch_bounds__(256)
void dtdecay_kernel(const float* __restrict__ X, const float* __restrict__ W_dt,
                    const float* __restrict__ dt_bias, const float* __restrict__ A_log,
                    float* __restrict__ dts, float* __restrict__ decs)
{
    __shared__ float Xs[16][64];
    __shared__ float Ws[64][16];
    const int tid = threadIdx.x;
    const int m0  = blockIdx.x * 16;
    const int h   = tid & 15;
    const int mi  = tid >> 4;

    float acc = 0.f;
    for (int k0 = 0; k0 < D_IN; k0 += 64) {
        __syncthreads();
        *(float4*)&Xs[tid >> 4][(tid & 15) * 4] =
            *(const float4*)&X[(size_t)(m0 + (tid >> 4)) * D_IN + k0 + (tid & 15) * 4];
        *(float4*)&Ws[tid >> 2][(tid & 3) * 4] =
            *(const float4*)&W_dt[(size_t)(k0 + (tid >> 2)) * NHEAD + (tid & 3) * 4];
        __syncthreads();
#pragma unroll
        for (int k = 0; k < 64; k++)
            acc = fmaf(Xs[mi][k], Ws[k][h], acc);
    }
    const int m = m0 + mi;
    float v  = acc + dt_bias[h];
    float dt = (v > 20.f) ? v : log1pf(expf(v));
    float A  = expf(A_log[h]);
    dts[m * NHEAD + h]  = dt;
    decs[m * NHEAD + h] = expf(-A * dt);
}

// ---------------- selective scan (rescaled-state, zero-init segment) --------
// g = h / cumprod(dec) within each 4-step group; renormalized at group end.
// Per step: g += s*B (fma2), y = cp * (C . g).
__global__ __launch_bounds__(128, 1)
void scan_kernel(const float* __restrict__ X, const float* __restrict__ Bm,
                 const float* __restrict__ Cm, const float* __restrict__ dts,
                 const float* __restrict__ decs,
                 __half* __restrict__ Yh, float* __restrict__ Yf,
                 ull* __restrict__ hstate, int t0, int t1, int store_state)
{
    const int bh = blockIdx.x;
    const int b  = bh >> 4;
    const int h  = bh & 15;
    const int tid = threadIdx.x;

    __shared__ __align__(16) float xb[4][4][PHEAD];
    __shared__ __align__(16) float Bb[4][4][NSTATE];
    __shared__ __align__(16) float Cb[4][4][NSTATE];
    __shared__ float sc[4][4][2];

    ull hs2[32];
#pragma unroll
    for (int i = 0; i < 32; i++) hs2[i] = 0ull;

    const int NP = (t1 - t0) >> 2;

    auto issue = [&](int g) {
        const int st = g & 3;
#pragma unroll
        for (int u = 0; u < 4; u++) {
            const int t = t0 + 4 * g + u;
            const size_t m = (size_t)t * BSZ + b;
            __pipeline_memcpy_async(&xb[st][u][tid], X + m * D_IN + h * PHEAD + tid, 4);
            if (tid < 64)
                __pipeline_memcpy_async(&Bb[st][u][tid], Bm + m * HN + h * NSTATE + tid, 4);
            else
                __pipeline_memcpy_async(&Cb[st][u][tid - 64], Cm + m * HN + h * NSTATE + (tid - 64), 4);
            if (tid == 0) __pipeline_memcpy_async(&sc[st][u][0], dts  + m * NHEAD + h, 4);
            if (tid == 1) __pipeline_memcpy_async(&sc[st][u][1], decs + m * NHEAD + h, 4);
        }
    };

    issue(0); __pipeline_commit();
    issue(1); __pipeline_commit();
    issue(2); __pipeline_commit();

    for (int g = 0; g < NP; g++) {
        const int st = g & 3;
        __pipeline_wait_prior(2);
        __syncthreads();
        if (g + 3 < NP) issue(g + 3);
        __pipeline_commit();

        float cp = 1.f;
#pragma unroll
        for (int u = 0; u < 4; u++) {
            const float dtv = sc[st][u][0];
            const float dec = sc[st][u][1];
            cp *= dec;
            const float s = dtv * xb[st][u][tid] / cp;
            const ull s2 = pk2(s, s);

            const longlong2* B2 = (const longlong2*)Bb[st][u];
            const longlong2* C2 = (const longlong2*)Cb[st][u];
            ull ya = 0ull, yb = 0ull;
#pragma unroll
            for (int j = 0; j < 16; j++) {
                longlong2 bv = B2[j];
                longlong2 cv = C2[j];
                hs2[2*j]   = fma2(s2, (ull)bv.x, hs2[2*j]);
                ya         = fma2(hs2[2*j],   (ull)cv.x, ya);
                hs2[2*j+1] = fma2(s2, (ull)bv.y, hs2[2*j+1]);
                yb         = fma2(hs2[2*j+1], (ull)cv.y, yb);
            }
            float a0, a1, c0, c1;
            upk2(a0, a1, ya);
            upk2(c0, c1, yb);
            const float y = cp * ((a0 + a1) + (c0 + c1));

            const int t = t0 + 4 * g + u;
            const size_t m = (size_t)t * BSZ + b;
            if (Yf)
                Yf[(m - (size_t)M_HALF) * D_IN + h * PHEAD + tid] = y;
            else
                Yh[m * D_IN + h * PHEAD + tid] = __float2half_rn(y);
        }
        // renormalize: g <- cp * g  (restores h scale at group boundary)
        const ull cp2 = pk2(cp, cp);
#pragma unroll
        for (int i = 0; i < 32; i++) hs2[i] = mul2(hs2[i], cp2);
    }

    if (store_state) {
        ull* hptr = hstate + ((size_t)bh * 128 + tid) * 32;
#pragma unroll
        for (int i = 0; i < 32; i++) hptr[i] = hs2[i];
    }
}

// ---------------- segment correction: y += cumdec(t) * (C_t . H_mid[p,:]) ---
__global__ __launch_bounds__(256)
void corr_kernel(const float* __restrict__ Cm, const float* __restrict__ decs,
                 const ull* __restrict__ hstate, const float* __restrict__ Yu,
                 __half* __restrict__ Yh)
{
    const int bh = blockIdx.x;
    const int b = bh >> 4, h = bh & 15;
    const int tid = threadIdx.x;
    const int lane = tid & 31, wid = tid >> 5;

    __shared__ __half H0s[128][72];
    __shared__ __half Cs[64][72];
    __shared__ float cd[256];

    const ull* hbase = hstate + (size_t)bh * 128 * 32;
#pragma unroll
    for (int i = 0; i < 16; i++) {
        int idx = tid * 16 + i;
        int p = idx >> 5, j = idx & 31;
        float f0, f1;
        upk2(f0, f1, hbase[(size_t)p * 32 + j]);
        H0s[p][2 * j]     = __float2half_rn(f0);
        H0s[p][2 * j + 1] = __float2half_rn(f1);
    }

    cd[tid] = decs[((size_t)(T_HALF + tid) * BSZ + b) * NHEAD + h];
    __syncthreads();
    for (int off = 1; off < 256; off <<= 1) {
        float v = cd[tid];
        float u = (tid >= off) ? cd[tid - off] : 1.f;
        __syncthreads();
        cd[tid] = v * u;
        __syncthreads();
    }

    const int warp_m = wid & 3;
    const int warp_n = wid >> 2;
    const uint32_t a_off = (uint32_t)((lane & 15) * 144 + (lane >> 4) * 16);
    const uint32_t b_off = (uint32_t)((lane & 7) * 144 + ((lane >> 3) & 1) * 16);
    const uint32_t cbase0 = smem_u32(&Cs[0][0]) + (uint32_t)(warp_m * 16) * 144 + a_off;
    const uint32_t hbase0 = smem_u32(&H0s[0][0]) + (uint32_t)(warp_n * 64) * 144 + b_off;
    const int r0 = lane >> 2, q0 = (lane & 3) * 2;

    for (int tt = 0; tt < 4; tt++) {
        __syncthreads();
#pragma unroll
        for (int i = 0; i < 16; i++) {
            int idx = tid * 16 + i;
            int j = idx >> 6, n = idx & 63;
            size_t m = (size_t)(T_HALF + tt * 64 + j) * BSZ + b;
            Cs[j][n] = __float2half_rn(Cm[m * HN + h * 64 + n]);
        }
        __syncthreads();

        float acc[8][4];
#pragma unroll
        for (int jg = 0; jg < 8; jg++)
#pragma unroll
            for (int q = 0; q < 4; q++) acc[jg][q] = 0.f;

#pragma unroll
        for (int ks = 0; ks < 4; ks++) {
            uint32_t af[4];
            ldsm_x4(af, cbase0 + ks * 32);
#pragma unroll
            for (int jg = 0; jg < 8; jg++) {
                uint32_t bf[2];
                ldsm_x2(bf, hbase0 + (uint32_t)(jg * 8) * 144 + ks * 32);
                mma_f16(acc[jg], af, bf);
            }
        }

#pragma unroll
        for (int jg = 0; jg < 8; jg++) {
            const int p = warp_n * 64 + jg * 8 + q0;
#pragma unroll
            for (int ii = 0; ii < 2; ii++) {
                const int tl = tt * 64 + warp_m * 16 + ii * 8 + r0;
                const size_t m = (size_t)(T_HALF + tl) * BSZ + b;
                const float c = cd[tl];
                const size_t uoff = (m - (size_t)M_HALF) * D_IN + h * 128 + p;
                float y0 = Yu[uoff]     + c * acc[jg][ii * 2];
                float y1 = Yu[uoff + 1] + c * acc[jg][ii * 2 + 1];
                __half2 hv = {__float2half_rn(y0), __float2half_rn(y1)};
                *(__half2*)&Yh[m * D_IN + h * 128 + p] = hv;
            }
        }
    }
}

// ---------------- policy head (fuses split-K sum + bias + relu) ------------
__global__ __launch_bounds__(256)
void head_kernel(const float* __restrict__ Zp, const float* __restrict__ b_yo,
                 const float* __restrict__ Wh, const float* __restrict__ bh,
                 float* __restrict__ out)
{
    __shared__ float Zs[4][NUNITS];
    __shared__ float Ws[64][NACT];
    const int tid = threadIdx.x;
    const int m0  = blockIdx.x * 4;
    const int n   = tid & 63;
    const int mi  = tid >> 6;

    {
        const int r  = tid >> 6;
        const int c4 = (tid & 63) * 4;
        float4 z0 = *(const float4*)&Zp[(size_t)(m0 + r) * NUNITS + c4];
        float4 z1 = *(const float4*)&Zp[(size_t)M_TOT * NUNITS + (size_t)(m0 + r) * NUNITS + c4];
        float4 by = *(const float4*)&b_yo[c4];
        float4 v;
        v.x = fmaxf(z0.x + z1.x + by.x, 0.f);
        v.y = fmaxf(z0.y + z1.y + by.y, 0.f);
        v.z = fmaxf(z0.z + z1.z + by.z, 0.f);
        v.w = fmaxf(z0.w + z1.w + by.w, 0.f);
        *(float4*)&Zs[r][c4] = v;
    }

    float acc = bh[n];
    for (int k0 = 0; k0 < NUNITS; k0 += 64) {
        __syncthreads();
#pragma unroll
        for (int j = 0; j < 4; j++) {
            int idx = tid + j * 256;
            int r = idx >> 4, c4 = (idx & 15) * 4;
            *(float4*)&Ws[r][c4] = *(const float4*)&Wh[(size_t)(k0 + r) * NACT + c4];
        }
        __syncthreads();
#pragma unroll
        for (int k = 0; k < 64; k++)
            acc = fmaf(Zs[mi][k0 + k], Ws[k][n], acc);
    }
    out[(size_t)(m0 + mi) * NACT + n] = acc;
}

// ---------------- launch (parallel segment scans + correction) --------------
extern "C" void kernel_launch(void* const* d_in, const int* in_sizes, int n_in,
                              void* d_out, int out_size)
{
    const float* obs     = (const float*)d_in[0];
    const float* W_in    = (const float*)d_in[1];
    const float* b_in    = (const float*)d_in[2];
    const float* A_log   = (const float*)d_in[3];
    const float* dt_bias = (const float*)d_in[4];
    const float* W_dt    = (const float*)d_in[5];
    const float* W_B     = (const float*)d_in[6];
    const float* W_C     = (const float*)d_in[7];
    const float* W_yo    = (const float*)d_in[8];
    const float* b_yo    = (const float*)d_in[9];
    const float* W_head  = (const float*)d_in[10];
    const float* b_head  = (const float*)d_in[11];
    float* out = (float*)d_out;

    float *X, *Bmp, *Cmp, *dts, *dec, *Yu, *Zp;
    __half *Xh, *Yh, *WBh, *WCh, *Wyoh;
    __nv_bfloat16 *obsh, *obsl, *Winh, *Winl;
    ull* hst;
    cudaGetSymbolAddress((void**)&X,    g_X);
    cudaGetSymbolAddress((void**)&Xh,   g_Xh);
    cudaGetSymbolAddress((void**)&Bmp,  g_Bm);
    cudaGetSymbolAddress((void**)&Cmp,  g_Cm);
    cudaGetSymbolAddress((void**)&dts,  g_dt);
    cudaGetSymbolAddress((void**)&dec,  g_dec);
    cudaGetSymbolAddress((void**)&Yh,   g_Yh);
    cudaGetSymbolAddress((void**)&Yu,   g_Yu);
    cudaGetSymbolAddress((void**)&Zp,   g_Zp);
    cudaGetSymbolAddress((void**)&hst,  g_hstate);
    cudaGetSymbolAddress((void**)&obsh, g_obs_hi);
    cudaGetSymbolAddress((void**)&obsl, g_obs_lo);
    cudaGetSymbolAddress((void**)&Winh, g_Win_hi);
    cudaGetSymbolAddress((void**)&Winl, g_Win_lo);
    cudaGetSymbolAddress((void**)&WBh,  g_WB_h);
    cudaGetSymbolAddress((void**)&WCh,  g_WC_h);
    cudaGetSymbolAddress((void**)&Wyoh, g_Wyo_h);

    static cudaStream_t sB = nullptr, sC = nullptr;
    static cudaEvent_t eFork, eWB, eWC, eWyo, eWin, eX, eB1, eB2, eC1, eC2, eD, eS1, eS2;
    if (!sB) {
        cudaStreamCreateWithFlags(&sB, cudaStreamNonBlocking);
        cudaStreamCreateWithFlags(&sC, cudaStreamNonBlocking);
        cudaEvent_t* evs[13] = {&eFork, &eWB, &eWC, &eWyo, &eWin, &eX,
                                &eB1, &eB2, &eC1, &eC2, &eD, &eS1, &eS2};
        for (int i = 0; i < 13; i++)
            cudaEventCreateWithFlags(evs[i], cudaEventDisableTiming);
        cudaFuncSetAttribute(mma_gemm_bf3<8>, cudaFuncAttributeMaxDynamicSharedMemorySize, SMEM_BF16);
        cudaFuncSetAttribute(mma_gemm_h1<64>, cudaFuncAttributeMaxDynamicSharedMemorySize, SMEM_F16_2);
        cudaFuncSetAttribute(mma_gemm_h1<32>, cudaFuncAttributeMaxDynamicSharedMemorySize, SMEM_F16_2);
    }

    cudaEventRecord(eFork, 0);
    cudaStreamWaitEvent(sB, eFork, 0);
    cudaStreamWaitEvent(sC, eFork, 0);

    // side-stream weight conversions
    transconv_h_kernel<<<dim3(HN / 32, D_IN / 32), dim3(32, 8), 0, sB>>>(W_B, WBh, D_IN, HN);
    cudaEventRecord(eWB, sB);
    transconv_kernel<<<dim3(D_IN / 32, OBS_DIM / 32), dim3(32, 8), 0, sC>>>(W_in, Winh, Winl, OBS_DIM, D_IN);
    cudaEventRecord(eWin, sC);
    transconv_h_kernel<<<dim3(HN / 32, D_IN / 32), dim3(32, 8), 0, sC>>>(W_C, WCh, D_IN, HN);
    cudaEventRecord(eWC, sC);
    transconv_h_kernel<<<dim3(NUNITS / 32, D_IN / 32), dim3(32, 8), 0, sC>>>(W_yo, Wyoh, D_IN, NUNITS);
    cudaEventRecord(eWyo, sC);

    // main: obs conversion, GEMM1
    rowconv_kernel<<<(M_TOT * OBS_DIM / 4 + 255) / 256, 256>>>(obs, obsh, obsl, M_TOT * OBS_DIM);
    cudaStreamWaitEvent(0, eWin, 0);
    mma_gemm_bf3<8><<<dim3(D_IN / 128, M_TOT / 128), 256, SMEM_BF16>>>(
        obsh, obsl, Winh, Winl, b_in, X, Xh, M_TOT, D_IN, OBS_DIM);
    cudaEventRecord(eX, 0);

    const size_t hA = (size_t)M_HALF * D_IN;
    const size_t hB = (size_t)M_HALF * HN;

    // B projection halves on main stream
    cudaStreamWaitEvent(0, eWB, 0);
    mma_gemm_h1<64><<<dim3(HN / 128, M_HALF / 128, 1), 256, SMEM_F16_2>>>(
        Xh, WBh, Bmp, M_HALF, HN, D_IN, 0);
    cudaEventRecord(eB1, 0);
    mma_gemm_h1<64><<<dim3(HN / 128, M_HALF / 128, 1), 256, SMEM_F16_2>>>(
        Xh + hA, WBh, Bmp + hB, M_HALF, HN, D_IN, 0);
    cudaEventRecord(eB2, 0);

    // C projection halves on stream B
    cudaStreamWaitEvent(sB, eX, 0);
    cudaStreamWaitEvent(sB, eWC, 0);
    mma_gemm_h1<64><<<dim3(HN / 128, M_HALF / 128, 1), 256, SMEM_F16_2, sB>>>(
        Xh, WCh, Cmp, M_HALF, HN, D_IN, 0);
    cudaEventRecord(eC1, sB);
    mma_gemm_h1<64><<<dim3(HN / 128, M_HALF / 128, 1), 256, SMEM_F16_2, sB>>>(
        Xh + hA, WCh, Cmp + hB, M_HALF, HN, D_IN, 0);
    cudaEventRecord(eC2, sB);

    // dt/decay on stream C
    cudaStreamWaitEvent(sC, eX, 0);
    dtdecay_kernel<<<M_TOT / 16, 256, 0, sC>>>(X, W_dt, dt_bias, A_log, dts, dec);
    cudaEventRecord(eD, sC);

    // scan seg0 on sC (zero init, writes Yh, stores H_mid)
    cudaStreamWaitEvent(sC, eB1, 0);
    cudaStreamWaitEvent(sC, eC1, 0);
    scan_kernel<<<BSZ * NHEAD, 128, 0, sC>>>(X, Bmp, Cmp, dts, dec, Yh, nullptr,
                                             hst, 0, T_HALF, 1);
    cudaEventRecord(eS1, sC);

    // scan seg1 on sB (zero init, writes Yu fp32), CONCURRENT with seg0
    cudaStreamWaitEvent(sB, eB2, 0);
    cudaStreamWaitEvent(sB, eD, 0);
    scan_kernel<<<BSZ * NHEAD, 128, 0, sB>>>(X, Bmp, Cmp, dts, dec, nullptr, Yu,
                                             hst, T_HALF, T_LEN, 0);
    // correction on sB (needs H_mid from seg0)
    cudaStreamWaitEvent(sB, eS1, 0);
    corr_kernel<<<128, 256, 0, sB>>>(Cmp, dec, hst, Yu, Yh);
    cudaEventRecord(eS2, sB);

    // yo projection halves (1-pass fp16, split-K=2) on main
    const size_t zstride = (size_t)M_TOT * NUNITS;
    cudaStreamWaitEvent(0, eWyo, 0);
    cudaStreamWaitEvent(0, eS1, 0);
    mma_gemm_h1<32><<<dim3(NUNITS / 128, M_HALF / 128, 2), 256, SMEM_F16_2>>>(
        Yh, Wyoh, Zp, M_HALF, NUNITS, D_IN, zstride);
    cudaStreamWaitEvent(0, eS2, 0);
    mma_gemm_h1<32><<<dim3(NUNITS / 128, M_HALF / 128, 2), 256, SMEM_F16_2>>>(
        Yh + hA, Wyoh, Zp + (size_t)M_HALF * NUNITS, M_HALF, NUNITS, D_IN, zstride);

    head_kernel<<<M_TOT / 4, 256>>>(Zp, b_yo, W_head, b_head, out);
}

// round 15
// speedup vs baseline: 1.0647x; 1.0647x over previous
#include <cuda_runtime.h>
#include <cuda_pipeline.h>
#include <cuda_bf16.h>
#include <cuda_fp16.h>
#include <math.h>
#include <stdint.h>

// ---------------- problem dims ----------------
#define T_LEN   512
#define BSZ     8
#define M_TOT   (T_LEN * BSZ)      // 4096
#define M_HALF  (M_TOT / 2)        // 2048
#define T_HALF  (T_LEN / 2)        // 256
#define OBS_DIM 256
#define D_IN    2048
#define NHEAD   16
#define NSTATE  64
#define PHEAD   128
#define NUNITS  256
#define NACT    64
#define HN      (NHEAD * NSTATE)    // 1024
#define WSCALE  32.0f
#define WISCALE (1.0f / 32.0f)

// ---------------- scratch ----------------
__device__ float          g_X   [M_TOT * D_IN];
__device__ __half         g_Xh  [M_TOT * D_IN];
__device__ float          g_Bm  [M_TOT * HN];
__device__ float          g_Cm  [M_TOT * HN];
__device__ float          g_dt  [M_TOT * NHEAD];
__device__ float          g_dec [M_TOT * NHEAD];
__device__ float          g_ide [M_TOT * NHEAD];         // 1/dec
__device__ __half         g_Yh  [M_TOT * D_IN];          // final fp16 Y
__device__ float          g_Yu  [M_HALF * D_IN];         // seg1 uncorrected y (fp32)
__device__ float          g_Zp  [2 * M_TOT * NUNITS];
__device__ unsigned long long g_hstate[128 * 128 * 32];  // H_mid (packed f32x2)
__device__ __nv_bfloat16  g_obs_hi[M_TOT * OBS_DIM];
__device__ __nv_bfloat16  g_obs_lo[M_TOT * OBS_DIM];
__device__ __nv_bfloat16  g_Win_hi[D_IN * OBS_DIM];
__device__ __nv_bfloat16  g_Win_lo[D_IN * OBS_DIM];
__device__ __half         g_WB_h [HN * D_IN];
__device__ __half         g_WC_h [HN * D_IN];
__device__ __half         g_Wyo_h[NUNITS * D_IN];

// ---------------- helpers ----------------
__device__ __forceinline__ uint32_t smem_u32(const void* p) {
    uint32_t a;
    asm("{ .reg .u64 t; cvta.to.shared.u64 t, %1; cvt.u32.u64 %0, t; }" : "=r"(a) : "l"(p));
    return a;
}
__device__ __forceinline__ void ldsm_x4(uint32_t* r, uint32_t addr) {
    asm volatile("ldmatrix.sync.aligned.m8n8.x4.shared.b16 {%0,%1,%2,%3}, [%4];"
                 : "=r"(r[0]), "=r"(r[1]), "=r"(r[2]), "=r"(r[3]) : "r"(addr));
}
__device__ __forceinline__ void ldsm_x2(uint32_t* r, uint32_t addr) {
    asm volatile("ldmatrix.sync.aligned.m8n8.x2.shared.b16 {%0,%1}, [%2];"
                 : "=r"(r[0]), "=r"(r[1]) : "r"(addr));
}
__device__ __forceinline__ void mma_bf16(float* c, const uint32_t* a, const uint32_t* b) {
    asm volatile("mma.sync.aligned.m16n8k16.row.col.f32.bf16.bf16.f32 "
                 "{%0,%1,%2,%3}, {%4,%5,%6,%7}, {%8,%9}, {%0,%1,%2,%3};"
                 : "+f"(c[0]), "+f"(c[1]), "+f"(c[2]), "+f"(c[3])
                 : "r"(a[0]), "r"(a[1]), "r"(a[2]), "r"(a[3]), "r"(b[0]), "r"(b[1]));
}
__device__ __forceinline__ void mma_f16(float* c, const uint32_t* a, const uint32_t* b) {
    asm volatile("mma.sync.aligned.m16n8k16.row.col.f32.f16.f16.f32 "
                 "{%0,%1,%2,%3}, {%4,%5,%6,%7}, {%8,%9}, {%0,%1,%2,%3};"
                 : "+f"(c[0]), "+f"(c[1]), "+f"(c[2]), "+f"(c[3])
                 : "r"(a[0]), "r"(a[1]), "r"(a[2]), "r"(a[3]), "r"(b[0]), "r"(b[1]));
}
typedef unsigned long long ull;
__device__ __forceinline__ ull pk2(float lo, float hi) {
    ull r; asm("mov.b64 %0, {%1, %2};" : "=l"(r) : "f"(lo), "f"(hi)); return r;
}
__device__ __forceinline__ void upk2(float& lo, float& hi, ull v) {
    asm("mov.b64 {%0, %1}, %2;" : "=f"(lo), "=f"(hi) : "l"(v));
}
__device__ __forceinline__ ull fma2(ull a, ull b, ull c) {
    ull d; asm("fma.rn.f32x2 %0, %1, %2, %3;" : "=l"(d) : "l"(a), "l"(b), "l"(c)); return d;
}
__device__ __forceinline__ ull mul2(ull a, ull b) {
    ull d; asm("mul.rn.f32x2 %0, %1, %2;" : "=l"(d) : "l"(a), "l"(b)); return d;
}

// ---------------- conversion kernels ----------------
__global__ void rowconv_kernel(const float* __restrict__ src,
                               __nv_bfloat16* __restrict__ hi,
                               __nv_bfloat16* __restrict__ lo, int n)
{
    int i = blockIdx.x * blockDim.x + threadIdx.x;
    if (i * 4 >= n) return;
    float4 v = *(const float4*)(src + i * 4);
    float vv[4] = {v.x, v.y, v.z, v.w};
#pragma unroll
    for (int j = 0; j < 4; j++) {
        __nv_bfloat16 h = __float2bfloat16(vv[j]);
        hi[i * 4 + j] = h;
        lo[i * 4 + j] = __float2bfloat16(vv[j] - __bfloat162float(h));
    }
}

__global__ void transconv_kernel(const float* __restrict__ W,
                                 __nv_bfloat16* __restrict__ Thi,
                                 __nv_bfloat16* __restrict__ Tlo, int K, int N)
{
    __shared__ float s[32][33];
    int tx = threadIdx.x, ty = threadIdx.y;
    int n0 = blockIdx.x * 32, k0 = blockIdx.y * 32;
#pragma unroll
    for (int i = 0; i < 4; i++)
        s[ty + i * 8][tx] = W[(size_t)(k0 + ty + i * 8) * N + n0 + tx];
    __syncthreads();
#pragma unroll
    for (int i = 0; i < 4; i++) {
        int n = n0 + ty + i * 8, k = k0 + tx;
        float v = s[tx][ty + i * 8];
        __nv_bfloat16 h = __float2bfloat16(v);
        Thi[(size_t)n * K + k] = h;
        Tlo[(size_t)n * K + k] = __float2bfloat16(v - __bfloat162float(h));
    }
}

__global__ void transconv_h_kernel(const float* __restrict__ W,
                                   __half* __restrict__ Th, int K, int N)
{
    __shared__ float s[32][33];
    int tx = threadIdx.x, ty = threadIdx.y;
    int n0 = blockIdx.x * 32, k0 = blockIdx.y * 32;
#pragma unroll
    for (int i = 0; i < 4; i++)
        s[ty + i * 8][tx] = W[(size_t)(k0 + ty + i * 8) * N + n0 + tx];
    __syncthreads();
#pragma unroll
    for (int i = 0; i < 4; i++) {
        int n = n0 + ty + i * 8, k = k0 + tx;
        Th[(size_t)n * K + k] = __float2half_rn(s[tx][ty + i * 8] * WSCALE);
    }
}

// ---------------- tile geometry ----------------
#define ROWB      80
#define TILE_B    (128 * ROWB)
#define BUF_B4    (4 * TILE_B)
#define SMEM_BF16 (2 * BUF_B4)
#define BUF_B2    (2 * TILE_B)
#define SMEM_F16_2 (2 * BUF_B2)

// ---------------- bf16x3 GEMM (GEMM1) ----------------
template<int KCHUNKS>
__global__ __launch_bounds__(256, 2)
void mma_gemm_bf3(const __nv_bfloat16* __restrict__ Ahi, const __nv_bfloat16* __restrict__ Alo,
                  const __nv_bfloat16* __restrict__ Bhi, const __nv_bfloat16* __restrict__ Blo,
                  const float* __restrict__ bias,
                  float* __restrict__ Cout, __half* __restrict__ Ch,
                  int M, int N, int K)
{
    extern __shared__ char smem[];
    const uint32_t sbase = smem_u32(smem);
    const int tid  = threadIdx.x;
    const int lane = tid & 31, wid = tid >> 5;
    const int warp_m = wid >> 2;
    const int warp_n = wid & 3;
    const int bn = blockIdx.x * 128;
    const int bm = blockIdx.y * 128;

    const __nv_bfloat16* srcs[4] = {Ahi, Alo, Bhi, Blo};

    auto load_chunk = [&](int c, int buf) {
#pragma unroll
        for (int w = 0; w < 4; w++) {
            const int rowbase = (w < 2) ? bm : bn;
            const __nv_bfloat16* src = srcs[w];
#pragma unroll
            for (int t = 0; t < 2; t++) {
                int idx = tid + t * 256;
                int row = idx >> 2, seg = idx & 3;
                char* dst = smem + buf * BUF_B4 + w * TILE_B + row * ROWB + seg * 16;
                const char* s = (const char*)src +
                    ((size_t)(rowbase + row) * K + (size_t)c * 32) * 2 + seg * 16;
                __pipeline_memcpy_async(dst, s, 16);
            }
        }
    };

    float acc[4][4][4];
#pragma unroll
    for (int i = 0; i < 4; i++)
#pragma unroll
        for (int j = 0; j < 4; j++)
#pragma unroll
            for (int q = 0; q < 4; q++) acc[i][j][q] = 0.f;

    load_chunk(0, 0);
    __pipeline_commit();
    __pipeline_wait_prior(0);
    __syncthreads();

    const uint32_t a_lane_off = (uint32_t)((lane & 15) * ROWB + (lane >> 4) * 16);
    const uint32_t b_lane_off = (uint32_t)((lane & 7) * ROWB + ((lane >> 3) & 1) * 16);

    for (int c = 0; c < KCHUNKS; c++) {
        if (c + 1 < KCHUNKS) { load_chunk(c + 1, (c + 1) & 1); __pipeline_commit(); }
        const uint32_t bufb = sbase + (c & 1) * BUF_B4;
#pragma unroll
        for (int s = 0; s < 2; s++) {
            uint32_t ah[4][4], al[4][4];
            const uint32_t ks = s * 32;
#pragma unroll
            for (int i = 0; i < 4; i++) {
                uint32_t ro = (uint32_t)((warp_m * 64 + i * 16) * ROWB) + ks + a_lane_off;
                ldsm_x4(ah[i], bufb + 0 * TILE_B + ro);
                ldsm_x4(al[i], bufb + 1 * TILE_B + ro);
            }
#pragma unroll
            for (int j = 0; j < 4; j++) {
                uint32_t bh[2], bl[2];
                uint32_t ro = (uint32_t)((warp_n * 32 + j * 8) * ROWB) + ks + b_lane_off;
                ldsm_x2(bh, bufb + 2 * TILE_B + ro);
                ldsm_x2(bl, bufb + 3 * TILE_B + ro);
#pragma unroll
                for (int i = 0; i < 4; i++) {
                    mma_bf16(acc[i][j], ah[i], bh);
                    mma_bf16(acc[i][j], ah[i], bl);
                    mma_bf16(acc[i][j], al[i], bh);
                }
            }
        }
        if (c + 1 < KCHUNKS) __pipeline_wait_prior(0);
        __syncthreads();
    }

    const int r0 = lane >> 2;
    const int q0 = (lane & 3) * 2;
#pragma unroll
    for (int j = 0; j < 4; j++) {
        const int n0 = bn + warp_n * 32 + j * 8 + q0;
        float b0 = bias[n0], b1 = bias[n0 + 1];
#pragma unroll
        for (int i = 0; i < 4; i++) {
            const int m0 = bm + warp_m * 64 + i * 16 + r0;
            float v0 = fmaxf(acc[i][j][0] + b0, 0.f);
            float v1 = fmaxf(acc[i][j][1] + b1, 0.f);
            float v2 = fmaxf(acc[i][j][2] + b0, 0.f);
            float v3 = fmaxf(acc[i][j][3] + b1, 0.f);
            *(float2*)&Cout[(size_t)m0 * N + n0]       = make_float2(v0, v1);
            *(float2*)&Cout[(size_t)(m0 + 8) * N + n0] = make_float2(v2, v3);
            __half2 hp0 = {__float2half_rn(v0), __float2half_rn(v1)};
            __half2 hp1 = {__float2half_rn(v2), __float2half_rn(v3)};
            *(__half2*)&Ch[(size_t)m0 * N + n0]       = hp0;
            *(__half2*)&Ch[(size_t)(m0 + 8) * N + n0] = hp1;
        }
    }
}

// ---------------- fp16 single-pass GEMM (B, C, yo) -------------------------
template<int KCHUNKS>
__global__ __launch_bounds__(256, 2)
void mma_gemm_h1(const __half* __restrict__ A, const __half* __restrict__ Wm,
                 float* __restrict__ Cout, int M, int N, int K, size_t zstride)
{
    extern __shared__ char smem[];
    const uint32_t sbase = smem_u32(smem);
    const int tid  = threadIdx.x;
    const int lane = tid & 31, wid = tid >> 5;
    const int warp_m = wid >> 2;
    const int warp_n = wid & 3;
    const int bn = blockIdx.x * 128;
    const int bm = blockIdx.y * 128;
    const int zoff = blockIdx.z * KCHUNKS;
    Cout += (size_t)blockIdx.z * zstride;

    const __half* srcs[2] = {A, Wm};

    auto load_chunk = [&](int gc, int buf) {
#pragma unroll
        for (int w = 0; w < 2; w++) {
            const int rowbase = (w == 0) ? bm : bn;
            const __half* src = srcs[w];
#pragma unroll
            for (int t = 0; t < 2; t++) {
                int idx = tid + t * 256;
                int row = idx >> 2, seg = idx & 3;
                char* dst = smem + buf * BUF_B2 + w * TILE_B + row * ROWB + seg * 16;
                const char* s = (const char*)src +
                    ((size_t)(rowbase + row) * K + (size_t)gc * 32) * 2 + seg * 16;
                __pipeline_memcpy_async(dst, s, 16);
            }
        }
    };

    float acc[4][4][4];
#pragma unroll
    for (int i = 0; i < 4; i++)
#pragma unroll
        for (int j = 0; j < 4; j++)
#pragma unroll
            for (int q = 0; q < 4; q++) acc[i][j][q] = 0.f;

    load_chunk(zoff, 0);
    __pipeline_commit();
    __pipeline_wait_prior(0);
    __syncthreads();

    const uint32_t a_lane_off = (uint32_t)((lane & 15) * ROWB + (lane >> 4) * 16);
    const uint32_t b_lane_off = (uint32_t)((lane & 7) * ROWB + ((lane >> 3) & 1) * 16);

    for (int c = 0; c < KCHUNKS; c++) {
        if (c + 1 < KCHUNKS) { load_chunk(zoff + c + 1, (c + 1) & 1); __pipeline_commit(); }
        const uint32_t bufb = sbase + (c & 1) * BUF_B2;
#pragma unroll
        for (int s = 0; s < 2; s++) {
            uint32_t af[4][4];
            const uint32_t ks = s * 32;
#pragma unroll
            for (int i = 0; i < 4; i++) {
                uint32_t ro = (uint32_t)((warp_m * 64 + i * 16) * ROWB) + ks + a_lane_off;
                ldsm_x4(af[i], bufb + 0 * TILE_B + ro);
            }
#pragma unroll
            for (int j = 0; j < 4; j++) {
                uint32_t wf[2];
                uint32_t ro = (uint32_t)((warp_n * 32 + j * 8) * ROWB) + ks + b_lane_off;
                ldsm_x2(wf, bufb + 1 * TILE_B + ro);
#pragma unroll
                for (int i = 0; i < 4; i++)
                    mma_f16(acc[i][j], af[i], wf);
            }
        }
        if (c + 1 < KCHUNKS) __pipeline_wait_prior(0);
        __syncthreads();
    }

    const int r0 = lane >> 2;
    const int q0 = (lane & 3) * 2;
#pragma unroll
    for (int j = 0; j < 4; j++) {
        const int n0 = bn + warp_n * 32 + j * 8 + q0;
#pragma unroll
        for (int i = 0; i < 4; i++) {
            const int m0 = bm + warp_m * 64 + i * 16 + r0;
            *(float2*)&Cout[(size_t)m0 * N + n0] =
                make_float2(acc[i][j][0] * WISCALE, acc[i][j][1] * WISCALE);
            *(float2*)&Cout[(size_t)(m0 + 8) * N + n0] =
                make_float2(acc[i][j][2] * WISCALE, acc[i][j][3] * WISCALE);
        }
    }
}

// ---------------- dt projection + softplus + decay (+inverse) --------------
__global__ __launch_bounds__(256)
void dtdecay_kernel(const float* __restrict__ X, const float* __restrict__ W_dt,
                    const float* __restrict__ dt_bias, const float* __restrict__ A_log,
                    float* __restrict__ dts, float* __restrict__ decs,
                    float* __restrict__ idecs)
{
    __shared__ float Xs[16][64];
    __shared__ float Ws[64][16];
    const int tid = threadIdx.x;
    const int m0  = blockIdx.x * 16;
    const int h   = tid & 15;
    const int mi  = tid >> 4;

    float acc = 0.f;
    for (int k0 = 0; k0 < D_IN; k0 += 64) {
        __syncthreads();
        *(float4*)&Xs[tid >> 4][(tid & 15) * 4] =
            *(const float4*)&X[(size_t)(m0 + (tid >> 4)) * D_IN + k0 + (tid & 15) * 4];
        *(float4*)&Ws[tid >> 2][(tid & 3) * 4] =
            *(const float4*)&W_dt[(size_t)(k0 + (tid >> 2)) * NHEAD + (tid & 3) * 4];
        __syncthreads();
#pragma unroll
        for (int k = 0; k < 64; k++)
            acc = fmaf(Xs[mi][k], Ws[k][h], acc);
    }
    const int m = m0 + mi;
    float v  = acc + dt_bias[h];
    float dt = (v > 20.f) ? v : log1pf(expf(v));
    float A  = expf(A_log[h]);
    float d  = expf(-A * dt);
    dts[m * NHEAD + h]   = dt;
    decs[m * NHEAD + h]  = d;
    idecs[m * NHEAD + h] = 1.0f / d;
}

// ---------------- selective scan (rescaled, division-free) ------------------
// Within each 4-step group: g = h/cp; g += s*B with s = dt*x*inv (inv via
// precomputed 1/dec); y = cp*(C.g); renorm g *= cp at group end.
__global__ __launch_bounds__(128, 1)
void scan_kernel(const float* __restrict__ X, const float* __restrict__ Bm,
                 const float* __restrict__ Cm, const float* __restrict__ dts,
                 const float* __restrict__ decs, const float* __restrict__ idecs,
                 __half* __restrict__ Yh, float* __restrict__ Yf,
                 ull* __restrict__ hstate, int t0, int t1, int store_state)
{
    const int bh = blockIdx.x;
    const int b  = bh >> 4;
    const int h  = bh & 15;
    const int tid = threadIdx.x;

    __shared__ __align__(16) float xb[4][4][PHEAD];
    __shared__ __align__(16) float Bb[4][4][NSTATE];
    __shared__ __align__(16) float Cb[4][4][NSTATE];
    __shared__ float sc[4][4][4];   // [stage][u][{dt,dec,idec}]

    ull hs2[32];
#pragma unroll
    for (int i = 0; i < 32; i++) hs2[i] = 0ull;

    const int NP = (t1 - t0) >> 2;

    auto issue = [&](int g) {
        const int st = g & 3;
#pragma unroll
        for (int u = 0; u < 4; u++) {
            const int t = t0 + 4 * g + u;
            const size_t m = (size_t)t * BSZ + b;
            __pipeline_memcpy_async(&xb[st][u][tid], X + m * D_IN + h * PHEAD + tid, 4);
            if (tid < 64)
                __pipeline_memcpy_async(&Bb[st][u][tid], Bm + m * HN + h * NSTATE + tid, 4);
            else
                __pipeline_memcpy_async(&Cb[st][u][tid - 64], Cm + m * HN + h * NSTATE + (tid - 64), 4);
            if (tid == 0) __pipeline_memcpy_async(&sc[st][u][0], dts   + m * NHEAD + h, 4);
            if (tid == 1) __pipeline_memcpy_async(&sc[st][u][1], decs  + m * NHEAD + h, 4);
            if (tid == 2) __pipeline_memcpy_async(&sc[st][u][2], idecs + m * NHEAD + h, 4);
        }
    };

    issue(0); __pipeline_commit();
    issue(1); __pipeline_commit();
    issue(2); __pipeline_commit();

    for (int g = 0; g < NP; g++) {
        const int st = g & 3;
        __pipeline_wait_prior(2);
        __syncthreads();
        if (g + 3 < NP) issue(g + 3);
        __pipeline_commit();

        float cp = 1.f, inv = 1.f;
#pragma unroll
        for (int u = 0; u < 4; u++) {
            const float dtv = sc[st][u][0];
            const float dec = sc[st][u][1];
            const float ide = sc[st][u][2];
            cp  *= dec;
            inv *= ide;
            const float s = (dtv * xb[st][u][tid]) * inv;
            const ull s2 = pk2(s, s);

            const longlong2* B2 = (const longlong2*)Bb[st][u];
            const longlong2* C2 = (const longlong2*)Cb[st][u];
            ull ya = 0ull, yb = 0ull;
#pragma unroll
            for (int j = 0; j < 16; j++) {
                longlong2 bv = B2[j];
                longlong2 cv = C2[j];
                hs2[2*j]   = fma2(s2, (ull)bv.x, hs2[2*j]);
                ya         = fma2(hs2[2*j],   (ull)cv.x, ya);
                hs2[2*j+1] = fma2(s2, (ull)bv.y, hs2[2*j+1]);
                yb         = fma2(hs2[2*j+1], (ull)cv.y, yb);
            }
            float a0, a1, c0, c1;
            upk2(a0, a1, ya);
            upk2(c0, c1, yb);
            const float y = cp * ((a0 + a1) + (c0 + c1));

            const int t = t0 + 4 * g + u;
            const size_t m = (size_t)t * BSZ + b;
            if (Yf)
                Yf[(m - (size_t)M_HALF) * D_IN + h * PHEAD + tid] = y;
            else
                Yh[m * D_IN + h * PHEAD + tid] = __float2half_rn(y);
        }
        const ull cp2 = pk2(cp, cp);
#pragma unroll
        for (int i = 0; i < 32; i++) hs2[i] = mul2(hs2[i], cp2);
    }

    if (store_state) {
        ull* hptr = hstate + ((size_t)bh * 128 + tid) * 32;
#pragma unroll
        for (int i = 0; i < 32; i++) hptr[i] = hs2[i];
    }
}

// ---------------- segment correction: y += cumdec(t) * (C_t . H_mid[p,:]) ---
__global__ __launch_bounds__(256)
void corr_kernel(const float* __restrict__ Cm, const float* __restrict__ decs,
                 const ull* __restrict__ hstate, const float* __restrict__ Yu,
                 __half* __restrict__ Yh)
{
    const int bh = blockIdx.x;
    const int b = bh >> 4, h = bh & 15;
    const int tid = threadIdx.x;
    const int lane = tid & 31, wid = tid >> 5;

    __shared__ __half H0s[128][72];
    __shared__ __half Cs[64][72];
    __shared__ float cd[256];

    const ull* hbase = hstate + (size_t)bh * 128 * 32;
#pragma unroll
    for (int i = 0; i < 16; i++) {
        int idx = tid * 16 + i;
        int p = idx >> 5, j = idx & 31;
        float f0, f1;
        upk2(f0, f1, hbase[(size_t)p * 32 + j]);
        H0s[p][2 * j]     = __float2half_rn(f0);
        H0s[p][2 * j + 1] = __float2half_rn(f1);
    }

    cd[tid] = decs[((size_t)(T_HALF + tid) * BSZ + b) * NHEAD + h];
    __syncthreads();
    for (int off = 1; off < 256; off <<= 1) {
        float v = cd[tid];
        float u = (tid >= off) ? cd[tid - off] : 1.f;
        __syncthreads();
        cd[tid] = v * u;
        __syncthreads();
    }

    const int warp_m = wid & 3;
    const int warp_n = wid >> 2;
    const uint32_t a_off = (uint32_t)((lane & 15) * 144 + (lane >> 4) * 16);
    const uint32_t b_off = (uint32_t)((lane & 7) * 144 + ((lane >> 3) & 1) * 16);
    const uint32_t cbase0 = smem_u32(&Cs[0][0]) + (uint32_t)(warp_m * 16) * 144 + a_off;
    const uint32_t hbase0 = smem_u32(&H0s[0][0]) + (uint32_t)(warp_n * 64) * 144 + b_off;
    const int r0 = lane >> 2, q0 = (lane & 3) * 2;

    for (int tt = 0; tt < 4; tt++) {
        __syncthreads();
#pragma unroll
        for (int i = 0; i < 16; i++) {
            int idx = tid * 16 + i;
            int j = idx >> 6, n = idx & 63;
            size_t m = (size_t)(T_HALF + tt * 64 + j) * BSZ + b;
            Cs[j][n] = __float2half_rn(Cm[m * HN + h * 64 + n]);
        }
        __syncthreads();

        float acc[8][4];
#pragma unroll
        for (int jg = 0; jg < 8; jg++)
#pragma unroll
            for (int q = 0; q < 4; q++) acc[jg][q] = 0.f;

#pragma unroll
        for (int ks = 0; ks < 4; ks++) {
            uint32_t af[4];
            ldsm_x4(af, cbase0 + ks * 32);
#pragma unroll
            for (int jg = 0; jg < 8; jg++) {
                uint32_t bf[2];
                ldsm_x2(bf, hbase0 + (uint32_t)(jg * 8) * 144 + ks * 32);
                mma_f16(acc[jg], af, bf);
            }
        }

#pragma unroll
        for (int jg = 0; jg < 8; jg++) {
            const int p = warp_n * 64 + jg * 8 + q0;
#pragma unroll
            for (int ii = 0; ii < 2; ii++) {
                const int tl = tt * 64 + warp_m * 16 + ii * 8 + r0;
                const size_t m = (size_t)(T_HALF + tl) * BSZ + b;
                const float c = cd[tl];
                const size_t uoff = (m - (size_t)M_HALF) * D_IN + h * 128 + p;
                float y0 = Yu[uoff]     + c * acc[jg][ii * 2];
                float y1 = Yu[uoff + 1] + c * acc[jg][ii * 2 + 1];
                __half2 hv = {__float2half_rn(y0), __float2half_rn(y1)};
                *(__half2*)&Yh[m * D_IN + h * 128 + p] = hv;
            }
        }
    }
}

// ---------------- policy head (fuses split-K sum + bias + relu) ------------
__global__ __launch_bounds__(256)
void head_kernel(const float* __restrict__ Zp, const float* __restrict__ b_yo,
                 const float* __restrict__ Wh, const float* __restrict__ bh,
                 float* __restrict__ out)
{
    __shared__ float Zs[4][NUNITS];
    __shared__ float Ws[64][NACT];
    const int tid = threadIdx.x;
    const int m0  = blockIdx.x * 4;
    const int n   = tid & 63;
    const int mi  = tid >> 6;

    {
        const int r  = tid >> 6;
        const int c4 = (tid & 63) * 4;
        float4 z0 = *(const float4*)&Zp[(size_t)(m0 + r) * NUNITS + c4];
        float4 z1 = *(const float4*)&Zp[(size_t)M_TOT * NUNITS + (size_t)(m0 + r) * NUNITS + c4];
        float4 by = *(const float4*)&b_yo[c4];
        float4 v;
        v.x = fmaxf(z0.x + z1.x + by.x, 0.f);
        v.y = fmaxf(z0.y + z1.y + by.y, 0.f);
        v.z = fmaxf(z0.z + z1.z + by.z, 0.f);
        v.w = fmaxf(z0.w + z1.w + by.w, 0.f);
        *(float4*)&Zs[r][c4] = v;
    }

    float acc = bh[n];
    for (int k0 = 0; k0 < NUNITS; k0 += 64) {
        __syncthreads();
#pragma unroll
        for (int j = 0; j < 4; j++) {
            int idx = tid + j * 256;
            int r = idx >> 4, c4 = (idx & 15) * 4;
            *(float4*)&Ws[r][c4] = *(const float4*)&Wh[(size_t)(k0 + r) * NACT + c4];
        }
        __syncthreads();
#pragma unroll
        for (int k = 0; k < 64; k++)
            acc = fmaf(Zs[mi][k0 + k], Ws[k][n], acc);
    }
    out[(size_t)(m0 + mi) * NACT + n] = acc;
}

// ---------------- launch (parallel segment scans + correction) --------------
extern "C" void kernel_launch(void* const* d_in, const int* in_sizes, int n_in,
                              void* d_out, int out_size)
{
    const float* obs     = (const float*)d_in[0];
    const float* W_in    = (const float*)d_in[1];
    const float* b_in    = (const float*)d_in[2];
    const float* A_log   = (const float*)d_in[3];
    const float* dt_bias = (const float*)d_in[4];
    const float* W_dt    = (const float*)d_in[5];
    const float* W_B     = (const float*)d_in[6];
    const float* W_C     = (const float*)d_in[7];
    const float* W_yo    = (const float*)d_in[8];
    const float* b_yo    = (const float*)d_in[9];
    const float* W_head  = (const float*)d_in[10];
    const float* b_head  = (const float*)d_in[11];
    float* out = (float*)d_out;

    float *X, *Bmp, *Cmp, *dts, *dec, *ide, *Yu, *Zp;
    __half *Xh, *Yh, *WBh, *WCh, *Wyoh;
    __nv_bfloat16 *obsh, *obsl, *Winh, *Winl;
    ull* hst;
    cudaGetSymbolAddress((void**)&X,    g_X);
    cudaGetSymbolAddress((void**)&Xh,   g_Xh);
    cudaGetSymbolAddress((void**)&Bmp,  g_Bm);
    cudaGetSymbolAddress((void**)&Cmp,  g_Cm);
    cudaGetSymbolAddress((void**)&dts,  g_dt);
    cudaGetSymbolAddress((void**)&dec,  g_dec);
    cudaGetSymbolAddress((void**)&ide,  g_ide);
    cudaGetSymbolAddress((void**)&Yh,   g_Yh);
    cudaGetSymbolAddress((void**)&Yu,   g_Yu);
    cudaGetSymbolAddress((void**)&Zp,   g_Zp);
    cudaGetSymbolAddress((void**)&hst,  g_hstate);
    cudaGetSymbolAddress((void**)&obsh, g_obs_hi);
    cudaGetSymbolAddress((void**)&obsl, g_obs_lo);
    cudaGetSymbolAddress((void**)&Winh, g_Win_hi);
    cudaGetSymbolAddress((void**)&Winl, g_Win_lo);
    cudaGetSymbolAddress((void**)&WBh,  g_WB_h);
    cudaGetSymbolAddress((void**)&WCh,  g_WC_h);
    cudaGetSymbolAddress((void**)&Wyoh, g_Wyo_h);

    static cudaStream_t sB = nullptr, sC = nullptr;
    static cudaEvent_t eFork, eWB, eWC, eWyo, eWin, eX, eB1, eB2, eC1, eC2, eD, eS1, eS2;
    if (!sB) {
        cudaStreamCreateWithFlags(&sB, cudaStreamNonBlocking);
        cudaStreamCreateWithFlags(&sC, cudaStreamNonBlocking);
        cudaEvent_t* evs[13] = {&eFork, &eWB, &eWC, &eWyo, &eWin, &eX,
                                &eB1, &eB2, &eC1, &eC2, &eD, &eS1, &eS2};
        for (int i = 0; i < 13; i++)
            cudaEventCreateWithFlags(evs[i], cudaEventDisableTiming);
        cudaFuncSetAttribute(mma_gemm_bf3<8>, cudaFuncAttributeMaxDynamicSharedMemorySize, SMEM_BF16);
        cudaFuncSetAttribute(mma_gemm_h1<64>, cudaFuncAttributeMaxDynamicSharedMemorySize, SMEM_F16_2);
        cudaFuncSetAttribute(mma_gemm_h1<32>, cudaFuncAttributeMaxDynamicSharedMemorySize, SMEM_F16_2);
    }

    cudaEventRecord(eFork, 0);
    cudaStreamWaitEvent(sB, eFork, 0);
    cudaStreamWaitEvent(sC, eFork, 0);

    // side-stream weight conversions
    transconv_h_kernel<<<dim3(HN / 32, D_IN / 32), dim3(32, 8), 0, sB>>>(W_B, WBh, D_IN, HN);
    cudaEventRecord(eWB, sB);
    transconv_kernel<<<dim3(D_IN / 32, OBS_DIM / 32), dim3(32, 8), 0, sC>>>(W_in, Winh, Winl, OBS_DIM, D_IN);
    cudaEventRecord(eWin, sC);
    transconv_h_kernel<<<dim3(HN / 32, D_IN / 32), dim3(32, 8), 0, sC>>>(W_C, WCh, D_IN, HN);
    cudaEventRecord(eWC, sC);
    transconv_h_kernel<<<dim3(NUNITS / 32, D_IN / 32), dim3(32, 8), 0, sC>>>(W_yo, Wyoh, D_IN, NUNITS);
    cudaEventRecord(eWyo, sC);

    // main: obs conversion, GEMM1
    rowconv_kernel<<<(M_TOT * OBS_DIM / 4 + 255) / 256, 256>>>(obs, obsh, obsl, M_TOT * OBS_DIM);
    cudaStreamWaitEvent(0, eWin, 0);
    mma_gemm_bf3<8><<<dim3(D_IN / 128, M_TOT / 128), 256, SMEM_BF16>>>(
        obsh, obsl, Winh, Winl, b_in, X, Xh, M_TOT, D_IN, OBS_DIM);
    cudaEventRecord(eX, 0);

    const size_t hA = (size_t)M_HALF * D_IN;
    const size_t hB = (size_t)M_HALF * HN;

    // B projection halves on main stream
    cudaStreamWaitEvent(0, eWB, 0);
    mma_gemm_h1<64><<<dim3(HN / 128, M_HALF / 128, 1), 256, SMEM_F16_2>>>(
        Xh, WBh, Bmp, M_HALF, HN, D_IN, 0);
    cudaEventRecord(eB1, 0);
    mma_gemm_h1<64><<<dim3(HN / 128, M_HALF / 128, 1), 256, SMEM_F16_2>>>(
        Xh + hA, WBh, Bmp + hB, M_HALF, HN, D_IN, 0);
    cudaEventRecord(eB2, 0);

    // C projection halves on stream B
    cudaStreamWaitEvent(sB, eX, 0);
    cudaStreamWaitEvent(sB, eWC, 0);
    mma_gemm_h1<64><<<dim3(HN / 128, M_HALF / 128, 1), 256, SMEM_F16_2, sB>>>(
        Xh, WCh, Cmp, M_HALF, HN, D_IN, 0);
    cudaEventRecord(eC1, sB);
    mma_gemm_h1<64><<<dim3(HN / 128, M_HALF / 128, 1), 256, SMEM_F16_2, sB>>>(
        Xh + hA, WCh, Cmp + hB, M_HALF, HN, D_IN, 0);
    cudaEventRecord(eC2, sB);

    // dt/decay on stream C
    cudaStreamWaitEvent(sC, eX, 0);
    dtdecay_kernel<<<M_TOT / 16, 256, 0, sC>>>(X, W_dt, dt_bias, A_log, dts, dec, ide);
    cudaEventRecord(eD, sC);

    // scan seg0 on sC (zero init, writes Yh, stores H_mid)
    cudaStreamWaitEvent(sC, eB1, 0);
    cudaStreamWaitEvent(sC, eC1, 0);
    scan_kernel<<<BSZ * NHEAD, 128, 0, sC>>>(X, Bmp, Cmp, dts, dec, ide, Yh, nullptr,
                                             hst, 0, T_HALF, 1);
    cudaEventRecord(eS1, sC);

    // scan seg1 on sB (zero init, writes Yu fp32), CONCURRENT with seg0
    cudaStreamWaitEvent(sB, eB2, 0);
    cudaStreamWaitEvent(sB, eD, 0);
    scan_kernel<<<BSZ * NHEAD, 128, 0, sB>>>(X, Bmp, Cmp, dts, dec, ide, nullptr, Yu,
                                             hst, T_HALF, T_LEN, 0);
    // correction on sB (needs H_mid from seg0)
    cudaStreamWaitEvent(sB, eS1, 0);
    corr_kernel<<<128, 256, 0, sB>>>(Cmp, dec, hst, Yu, Yh);
    cudaEventRecord(eS2, sB);

    // yo projection halves (1-pass fp16, split-K=2) on main
    const size_t zstride = (size_t)M_TOT * NUNITS;
    cudaStreamWaitEvent(0, eWyo, 0);
    cudaStreamWaitEvent(0, eS1, 0);
    mma_gemm_h1<32><<<dim3(NUNITS / 128, M_HALF / 128, 2), 256, SMEM_F16_2>>>(
        Yh, Wyoh, Zp, M_HALF, NUNITS, D_IN, zstride);
    cudaStreamWaitEvent(0, eS2, 0);
    mma_gemm_h1<32><<<dim3(NUNITS / 128, M_HALF / 128, 2), 256, SMEM_F16_2>>>(
        Yh + hA, Wyoh, Zp + (size_t)M_HALF * NUNITS, M_HALF, NUNITS, D_IN, zstride);

    head_kernel<<<M_TOT / 4, 256>>>(Zp, b_yo, W_head, b_head, out);
}

// round 16
// speedup vs baseline: 1.1332x; 1.0643x over previous
#include <cuda_runtime.h>
#include <cuda_pipeline.h>
#include <cuda_bf16.h>
#include <cuda_fp16.h>
#include <math.h>
#include <stdint.h>

// ---------------- problem dims ----------------
#define T_LEN   512
#define BSZ     8
#define M_TOT   (T_LEN * BSZ)      // 4096
#define M_HALF  (M_TOT / 2)        // 2048
#define T_HALF  (T_LEN / 2)        // 256
#define OBS_DIM 256
#define D_IN    2048
#define NHEAD   16
#define NSTATE  64
#define PHEAD   128
#define NUNITS  256
#define NACT    64
#define HN      (NHEAD * NSTATE)    // 1024
#define WSCALE  32.0f
#define WISCALE (1.0f / 32.0f)

// ---------------- scratch ----------------
__device__ float          g_X   [M_TOT * D_IN];
__device__ __half         g_Xh  [M_TOT * D_IN];
__device__ float          g_Bm  [M_TOT * HN];
__device__ float          g_Cm  [M_TOT * HN];
__device__ float          g_dt  [M_TOT * NHEAD];
__device__ float          g_dec [M_TOT * NHEAD];
__device__ __half         g_Yh  [M_TOT * D_IN];          // final fp16 Y
__device__ __half         g_Yu  [M_HALF * D_IN];         // seg1 uncorrected y (fp16)
__device__ float          g_Zp  [2 * M_TOT * NUNITS];
__device__ unsigned long long g_hstate[128 * 128 * 32];  // H_mid (packed f32x2)
__device__ __half         g_obs_hi[M_TOT * OBS_DIM];
__device__ __half         g_obs_lo[M_TOT * OBS_DIM];
__device__ __half         g_Win_h[D_IN * OBS_DIM];       // fp16 x32
__device__ __half         g_WB_h [HN * D_IN];
__device__ __half         g_WC_h [HN * D_IN];
__device__ __half         g_Wyo_h[NUNITS * D_IN];

// ---------------- helpers ----------------
__device__ __forceinline__ uint32_t smem_u32(const void* p) {
    uint32_t a;
    asm("{ .reg .u64 t; cvta.to.shared.u64 t, %1; cvt.u32.u64 %0, t; }" : "=r"(a) : "l"(p));
    return a;
}
__device__ __forceinline__ void ldsm_x4(uint32_t* r, uint32_t addr) {
    asm volatile("ldmatrix.sync.aligned.m8n8.x4.shared.b16 {%0,%1,%2,%3}, [%4];"
                 : "=r"(r[0]), "=r"(r[1]), "=r"(r[2]), "=r"(r[3]) : "r"(addr));
}
__device__ __forceinline__ void ldsm_x2(uint32_t* r, uint32_t addr) {
    asm volatile("ldmatrix.sync.aligned.m8n8.x2.shared.b16 {%0,%1}, [%2];"
                 : "=r"(r[0]), "=r"(r[1]) : "r"(addr));
}
__device__ __forceinline__ void mma_f16(float* c, const uint32_t* a, const uint32_t* b) {
    asm volatile("mma.sync.aligned.m16n8k16.row.col.f32.f16.f16.f32 "
                 "{%0,%1,%2,%3}, {%4,%5,%6,%7}, {%8,%9}, {%0,%1,%2,%3};"
                 : "+f"(c[0]), "+f"(c[1]), "+f"(c[2]), "+f"(c[3])
                 : "r"(a[0]), "r"(a[1]), "r"(a[2]), "r"(a[3]), "r"(b[0]), "r"(b[1]));
}
typedef unsigned long long ull;
__device__ __forceinline__ ull pk2(float lo, float hi) {
    ull r; asm("mov.b64 %0, {%1, %2};" : "=l"(r) : "f"(lo), "f"(hi)); return r;
}
__device__ __forceinline__ void upk2(float& lo, float& hi, ull v) {
    asm("mov.b64 {%0, %1}, %2;" : "=f"(lo), "=f"(hi) : "l"(v));
}
__device__ __forceinline__ ull fma2(ull a, ull b, ull c) {
    ull d; asm("fma.rn.f32x2 %0, %1, %2, %3;" : "=l"(d) : "l"(a), "l"(b), "l"(c)); return d;
}
__device__ __forceinline__ ull mul2(ull a, ull b) {
    ull d; asm("mul.rn.f32x2 %0, %1, %2;" : "=l"(d) : "l"(a), "l"(b)); return d;
}

// ---------------- conversion kernels ----------------
__global__ void rowconv_kernel(const float* __restrict__ src,
                               __half* __restrict__ hi,
                               __half* __restrict__ lo, int n)
{
    int i = blockIdx.x * blockDim.x + threadIdx.x;
    if (i * 4 >= n) return;
    float4 v = *(const float4*)(src + i * 4);
    float vv[4] = {v.x, v.y, v.z, v.w};
#pragma unroll
    for (int j = 0; j < 4; j++) {
        __half h = __float2half_rn(vv[j]);
        hi[i * 4 + j] = h;
        lo[i * 4 + j] = __float2half_rn(vv[j] - __half2float(h));
    }
}

__global__ void transconv_h_kernel(const float* __restrict__ W,
                                   __half* __restrict__ Th, int K, int N)
{
    __shared__ float s[32][33];
    int tx = threadIdx.x, ty = threadIdx.y;
    int n0 = blockIdx.x * 32, k0 = blockIdx.y * 32;
#pragma unroll
    for (int i = 0; i < 4; i++)
        s[ty + i * 8][tx] = W[(size_t)(k0 + ty + i * 8) * N + n0 + tx];
    __syncthreads();
#pragma unroll
    for (int i = 0; i < 4; i++) {
        int n = n0 + ty + i * 8, k = k0 + tx;
        Th[(size_t)n * K + k] = __float2half_rn(s[tx][ty + i * 8] * WSCALE);
    }
}

// ---------------- tile geometry ----------------
#define ROWB      80
#define TILE_B    (128 * ROWB)
#define BUF_B2    (2 * TILE_B)
#define SMEM_F16_2 (2 * BUF_B2)
#define BUF_B3    (3 * TILE_B)
#define SMEM_F16_3 (2 * BUF_B3)

// ---------------- fp16 2-pass GEMM1 (bias+relu, X fp32 + Xh fp16) ----------
template<int KCHUNKS>
__global__ __launch_bounds__(256, 2)
void mma_gemm1h(const __half* __restrict__ Ahi, const __half* __restrict__ Alo,
                const __half* __restrict__ Wm, const float* __restrict__ bias,
                float* __restrict__ Cout, __half* __restrict__ Ch,
                int M, int N, int K)
{
    extern __shared__ char smem[];
    const uint32_t sbase = smem_u32(smem);
    const int tid  = threadIdx.x;
    const int lane = tid & 31, wid = tid >> 5;
    const int warp_m = wid >> 2;
    const int warp_n = wid & 3;
    const int bn = blockIdx.x * 128;
    const int bm = blockIdx.y * 128;

    const __half* srcs[3] = {Ahi, Alo, Wm};

    auto load_chunk = [&](int c, int buf) {
#pragma unroll
        for (int w = 0; w < 3; w++) {
            const int rowbase = (w < 2) ? bm : bn;
            const __half* src = srcs[w];
#pragma unroll
            for (int t = 0; t < 2; t++) {
                int idx = tid + t * 256;
                int row = idx >> 2, seg = idx & 3;
                char* dst = smem + buf * BUF_B3 + w * TILE_B + row * ROWB + seg * 16;
                const char* s = (const char*)src +
                    ((size_t)(rowbase + row) * K + (size_t)c * 32) * 2 + seg * 16;
                __pipeline_memcpy_async(dst, s, 16);
            }
        }
    };

    float acc[4][4][4];
#pragma unroll
    for (int i = 0; i < 4; i++)
#pragma unroll
        for (int j = 0; j < 4; j++)
#pragma unroll
            for (int q = 0; q < 4; q++) acc[i][j][q] = 0.f;

    load_chunk(0, 0);
    __pipeline_commit();
    __pipeline_wait_prior(0);
    __syncthreads();

    const uint32_t a_lane_off = (uint32_t)((lane & 15) * ROWB + (lane >> 4) * 16);
    const uint32_t b_lane_off = (uint32_t)((lane & 7) * ROWB + ((lane >> 3) & 1) * 16);

    for (int c = 0; c < KCHUNKS; c++) {
        if (c + 1 < KCHUNKS) { load_chunk(c + 1, (c + 1) & 1); __pipeline_commit(); }
        const uint32_t bufb = sbase + (c & 1) * BUF_B3;
#pragma unroll
        for (int s = 0; s < 2; s++) {
            uint32_t ah[4][4], al[4][4];
            const uint32_t ks = s * 32;
#pragma unroll
            for (int i = 0; i < 4; i++) {
                uint32_t ro = (uint32_t)((warp_m * 64 + i * 16) * ROWB) + ks + a_lane_off;
                ldsm_x4(ah[i], bufb + 0 * TILE_B + ro);
                ldsm_x4(al[i], bufb + 1 * TILE_B + ro);
            }
#pragma unroll
            for (int j = 0; j < 4; j++) {
                uint32_t wf[2];
                uint32_t ro = (uint32_t)((warp_n * 32 + j * 8) * ROWB) + ks + b_lane_off;
                ldsm_x2(wf, bufb + 2 * TILE_B + ro);
#pragma unroll
                for (int i = 0; i < 4; i++) {
                    mma_f16(acc[i][j], ah[i], wf);
                    mma_f16(acc[i][j], al[i], wf);
                }
            }
        }
        if (c + 1 < KCHUNKS) __pipeline_wait_prior(0);
        __syncthreads();
    }

    const int r0 = lane >> 2;
    const int q0 = (lane & 3) * 2;
#pragma unroll
    for (int j = 0; j < 4; j++) {
        const int n0 = bn + warp_n * 32 + j * 8 + q0;
        float b0 = bias[n0], b1 = bias[n0 + 1];
#pragma unroll
        for (int i = 0; i < 4; i++) {
            const int m0 = bm + warp_m * 64 + i * 16 + r0;
            float v0 = fmaxf(acc[i][j][0] * WISCALE + b0, 0.f);
            float v1 = fmaxf(acc[i][j][1] * WISCALE + b1, 0.f);
            float v2 = fmaxf(acc[i][j][2] * WISCALE + b0, 0.f);
            float v3 = fmaxf(acc[i][j][3] * WISCALE + b1, 0.f);
            *(float2*)&Cout[(size_t)m0 * N + n0]       = make_float2(v0, v1);
            *(float2*)&Cout[(size_t)(m0 + 8) * N + n0] = make_float2(v2, v3);
            __half2 hp0 = {__float2half_rn(v0), __float2half_rn(v1)};
            __half2 hp1 = {__float2half_rn(v2), __float2half_rn(v3)};
            *(__half2*)&Ch[(size_t)m0 * N + n0]       = hp0;
            *(__half2*)&Ch[(size_t)(m0 + 8) * N + n0] = hp1;
        }
    }
}

// ---------------- fp16 single-pass GEMM (B, C, yo) -------------------------
template<int KCHUNKS>
__global__ __launch_bounds__(256, 2)
void mma_gemm_h1(const __half* __restrict__ A, const __half* __restrict__ Wm,
                 float* __restrict__ Cout, int M, int N, int K, size_t zstride)
{
    extern __shared__ char smem[];
    const uint32_t sbase = smem_u32(smem);
    const int tid  = threadIdx.x;
    const int lane = tid & 31, wid = tid >> 5;
    const int warp_m = wid >> 2;
    const int warp_n = wid & 3;
    const int bn = blockIdx.x * 128;
    const int bm = blockIdx.y * 128;
    const int zoff = blockIdx.z * KCHUNKS;
    Cout += (size_t)blockIdx.z * zstride;

    const __half* srcs[2] = {A, Wm};

    auto load_chunk = [&](int gc, int buf) {
#pragma unroll
        for (int w = 0; w < 2; w++) {
            const int rowbase = (w == 0) ? bm : bn;
            const __half* src = srcs[w];
#pragma unroll
            for (int t = 0; t < 2; t++) {
                int idx = tid + t * 256;
                int row = idx >> 2, seg = idx & 3;
                char* dst = smem + buf * BUF_B2 + w * TILE_B + row * ROWB + seg * 16;
                const char* s = (const char*)src +
                    ((size_t)(rowbase + row) * K + (size_t)gc * 32) * 2 + seg * 16;
                __pipeline_memcpy_async(dst, s, 16);
            }
        }
    };

    float acc[4][4][4];
#pragma unroll
    for (int i = 0; i < 4; i++)
#pragma unroll
        for (int j = 0; j < 4; j++)
#pragma unroll
            for (int q = 0; q < 4; q++) acc[i][j][q] = 0.f;

    load_chunk(zoff, 0);
    __pipeline_commit();
    __pipeline_wait_prior(0);
    __syncthreads();

    const uint32_t a_lane_off = (uint32_t)((lane & 15) * ROWB + (lane >> 4) * 16);
    const uint32_t b_lane_off = (uint32_t)((lane & 7) * ROWB + ((lane >> 3) & 1) * 16);

    for (int c = 0; c < KCHUNKS; c++) {
        if (c + 1 < KCHUNKS) { load_chunk(zoff + c + 1, (c + 1) & 1); __pipeline_commit(); }
        const uint32_t bufb = sbase + (c & 1) * BUF_B2;
#pragma unroll
        for (int s = 0; s < 2; s++) {
            uint32_t af[4][4];
            const uint32_t ks = s * 32;
#pragma unroll
            for (int i = 0; i < 4; i++) {
                uint32_t ro = (uint32_t)((warp_m * 64 + i * 16) * ROWB) + ks + a_lane_off;
                ldsm_x4(af[i], bufb + 0 * TILE_B + ro);
            }
#pragma unroll
            for (int j = 0; j < 4; j++) {
                uint32_t wf[2];
                uint32_t ro = (uint32_t)((warp_n * 32 + j * 8) * ROWB) + ks + b_lane_off;
                ldsm_x2(wf, bufb + 1 * TILE_B + ro);
#pragma unroll
                for (int i = 0; i < 4; i++)
                    mma_f16(acc[i][j], af[i], wf);
            }
        }
        if (c + 1 < KCHUNKS) __pipeline_wait_prior(0);
        __syncthreads();
    }

    const int r0 = lane >> 2;
    const int q0 = (lane & 3) * 2;
#pragma unroll
    for (int j = 0; j < 4; j++) {
        const int n0 = bn + warp_n * 32 + j * 8 + q0;
#pragma unroll
        for (int i = 0; i < 4; i++) {
            const int m0 = bm + warp_m * 64 + i * 16 + r0;
            *(float2*)&Cout[(size_t)m0 * N + n0] =
                make_float2(acc[i][j][0] * WISCALE, acc[i][j][1] * WISCALE);
            *(float2*)&Cout[(size_t)(m0 + 8) * N + n0] =
                make_float2(acc[i][j][2] * WISCALE, acc[i][j][3] * WISCALE);
        }
    }
}

// ---------------- dt projection + softplus + decay ----------------
__global__ __launch_bounds__(256)
void dtdecay_kernel(const float* __restrict__ X, const float* __restrict__ W_dt,
                    const float* __restrict__ dt_bias, const float* __restrict__ A_log,
                    float* __restrict__ dts, float* __restrict__ decs)
{
    __shared__ float Xs[16][64];
    __shared__ float Ws[64][16];
    const int tid = threadIdx.x;
    const int m0  = blockIdx.x * 16;
    const int h   = tid & 15;
    const int mi  = tid >> 4;

    float acc = 0.f;
    for (int k0 = 0; k0 < D_IN; k0 += 64) {
        __syncthreads();
        *(float4*)&Xs[tid >> 4][(tid & 15) * 4] =
            *(const float4*)&X[(size_t)(m0 + (tid >> 4)) * D_IN + k0 + (tid & 15) * 4];
        *(float4*)&Ws[tid >> 2][(tid & 3) * 4] =
            *(const float4*)&W_dt[(size_t)(k0 + (tid >> 2)) * NHEAD + (tid & 3) * 4];
        __syncthreads();
#pragma unroll
        for (int k = 0; k < 64; k++)
            acc = fmaf(Xs[mi][k], Ws[k][h], acc);
    }
    const int m = m0 + mi;
    float v  = acc + dt_bias[h];
    float dt = (v > 20.f) ? v : log1pf(expf(v));
    float A  = expf(A_log[h]);
    dts[m * NHEAD + h]  = dt;
    decs[m * NHEAD + h] = expf(-A * dt);
}

// ---------------- selective scan (round-13 form, zero-init segment) ---------
__global__ __launch_bounds__(128, 1)
void scan_kernel(const float* __restrict__ X, const float* __restrict__ Bm,
                 const float* __restrict__ Cm, const float* __restrict__ dts,
                 const float* __restrict__ decs,
                 __half* __restrict__ Yh, __half* __restrict__ Yu,
                 ull* __restrict__ hstate, int t0, int t1, int store_state)
{
    const int bh = blockIdx.x;
    const int b  = bh >> 4;
    const int h  = bh & 15;
    const int tid = threadIdx.x;

    __shared__ __align__(16) float xb[4][4][PHEAD];
    __shared__ __align__(16) float Bb[4][4][NSTATE];
    __shared__ __align__(16) float Cb[4][4][NSTATE];
    __shared__ float sc[4][4][2];

    ull hs2[32];
#pragma unroll
    for (int i = 0; i < 32; i++) hs2[i] = 0ull;

    const int NP = (t1 - t0) >> 2;

    auto issue = [&](int g) {
        const int st = g & 3;
#pragma unroll
        for (int u = 0; u < 4; u++) {
            const int t = t0 + 4 * g + u;
            const size_t m = (size_t)t * BSZ + b;
            __pipeline_memcpy_async(&xb[st][u][tid], X + m * D_IN + h * PHEAD + tid, 4);
            if (tid < 64)
                __pipeline_memcpy_async(&Bb[st][u][tid], Bm + m * HN + h * NSTATE + tid, 4);
            else
                __pipeline_memcpy_async(&Cb[st][u][tid - 64], Cm + m * HN + h * NSTATE + (tid - 64), 4);
            if (tid == 0) __pipeline_memcpy_async(&sc[st][u][0], dts  + m * NHEAD + h, 4);
            if (tid == 1) __pipeline_memcpy_async(&sc[st][u][1], decs + m * NHEAD + h, 4);
        }
    };

    issue(0); __pipeline_commit();
    issue(1); __pipeline_commit();
    issue(2); __pipeline_commit();

    for (int g = 0; g < NP; g++) {
        const int st = g & 3;
        __pipeline_wait_prior(2);
        __syncthreads();
        if (g + 3 < NP) issue(g + 3);
        __pipeline_commit();

#pragma unroll
        for (int u = 0; u < 4; u++) {
            const float dtv = sc[st][u][0];
            const float dec = sc[st][u][1];
            const float cc  = dtv * xb[st][u][tid];
            const ull dec2 = pk2(dec, dec);
            const ull cc2  = pk2(cc, cc);

            const longlong2* B2 = (const longlong2*)Bb[st][u];
            const longlong2* C2 = (const longlong2*)Cb[st][u];
            ull ya = 0ull, yb = 0ull;
#pragma unroll
            for (int j = 0; j < 16; j++) {
                longlong2 bv = B2[j];
                longlong2 cv = C2[j];
                hs2[2*j]   = fma2(dec2, hs2[2*j],   mul2(cc2, (ull)bv.x));
                ya         = fma2(hs2[2*j],   (ull)cv.x, ya);
                hs2[2*j+1] = fma2(dec2, hs2[2*j+1], mul2(cc2, (ull)bv.y));
                yb         = fma2(hs2[2*j+1], (ull)cv.y, yb);
            }
            float a0, a1, c0, c1;
            upk2(a0, a1, ya);
            upk2(c0, c1, yb);
            const float y = (a0 + a1) + (c0 + c1);

            const int t = t0 + 4 * g + u;
            const size_t m = (size_t)t * BSZ + b;
            if (Yu)
                Yu[(m - (size_t)M_HALF) * D_IN + h * PHEAD + tid] = __float2half_rn(y);
            else
                Yh[m * D_IN + h * PHEAD + tid] = __float2half_rn(y);
        }
    }

    if (store_state) {
        ull* hptr = hstate + ((size_t)bh * 128 + tid) * 32;
#pragma unroll
        for (int i = 0; i < 32; i++) hptr[i] = hs2[i];
    }
}

// ---------------- segment correction: y += cumdec(t) * (C_t . H_mid[p,:]) ---
__global__ __launch_bounds__(256)
void corr_kernel(const float* __restrict__ Cm, const float* __restrict__ decs,
                 const ull* __restrict__ hstate, const __half* __restrict__ Yu,
                 __half* __restrict__ Yh)
{
    const int bh = blockIdx.x;
    const int b = bh >> 4, h = bh & 15;
    const int tid = threadIdx.x;
    const int lane = tid & 31, wid = tid >> 5;

    __shared__ __half H0s[128][72];
    __shared__ __half Cs[64][72];
    __shared__ float cd[256];

    const ull* hbase = hstate + (size_t)bh * 128 * 32;
#pragma unroll
    for (int i = 0; i < 16; i++) {
        int idx = tid * 16 + i;
        int p = idx >> 5, j = idx & 31;
        float f0, f1;
        upk2(f0, f1, hbase[(size_t)p * 32 + j]);
        H0s[p][2 * j]     = __float2half_rn(f0);
        H0s[p][2 * j + 1] = __float2half_rn(f1);
    }

    cd[tid] = decs[((size_t)(T_HALF + tid) * BSZ + b) * NHEAD + h];
    __syncthreads();
    for (int off = 1; off < 256; off <<= 1) {
        float v = cd[tid];
        float u = (tid >= off) ? cd[tid - off] : 1.f;
        __syncthreads();
        cd[tid] = v * u;
        __syncthreads();
    }

    const int warp_m = wid & 3;
    const int warp_n = wid >> 2;
    const uint32_t a_off = (uint32_t)((lane & 15) * 144 + (lane >> 4) * 16);
    const uint32_t b_off = (uint32_t)((lane & 7) * 144 + ((lane >> 3) & 1) * 16);
    const uint32_t cbase0 = smem_u32(&Cs[0][0]) + (uint32_t)(warp_m * 16) * 144 + a_off;
    const uint32_t hbase0 = smem_u32(&H0s[0][0]) + (uint32_t)(warp_n * 64) * 144 + b_off;
    const int r0 = lane >> 2, q0 = (lane & 3) * 2;

    for (int tt = 0; tt < 4; tt++) {
        __syncthreads();
#pragma unroll
        for (int i = 0; i < 16; i++) {
            int idx = tid * 16 + i;
            int j = idx >> 6, n = idx & 63;
            size_t m = (size_t)(T_HALF + tt * 64 + j) * BSZ + b;
            Cs[j][n] = __float2half_rn(Cm[m * HN + h * 64 + n]);
        }
        __syncthreads();

        float acc[8][4];
#pragma unroll
        for (int jg = 0; jg < 8; jg++)
#pragma unroll
            for (int q = 0; q < 4; q++) acc[jg][q] = 0.f;

#pragma unroll
        for (int ks = 0; ks < 4; ks++) {
            uint32_t af[4];
            ldsm_x4(af, cbase0 + ks * 32);
#pragma unroll
            for (int jg = 0; jg < 8; jg++) {
                uint32_t bf[2];
                ldsm_x2(bf, hbase0 + (uint32_t)(jg * 8) * 144 + ks * 32);
                mma_f16(acc[jg], af, bf);
            }
        }

#pragma unroll
        for (int jg = 0; jg < 8; jg++) {
            const int p = warp_n * 64 + jg * 8 + q0;
#pragma unroll
            for (int ii = 0; ii < 2; ii++) {
                const int tl = tt * 64 + warp_m * 16 + ii * 8 + r0;
                const size_t m = (size_t)(T_HALF + tl) * BSZ + b;
                const float c = cd[tl];
                const size_t uoff = (m - (size_t)M_HALF) * D_IN + h * 128 + p;
                __half2 uv = *(const __half2*)&Yu[uoff];
                float2 uf = __half22float2(uv);
                float y0 = uf.x + c * acc[jg][ii * 2];
                float y1 = uf.y + c * acc[jg][ii * 2 + 1];
                __half2 hv = {__float2half_rn(y0), __float2half_rn(y1)};
                *(__half2*)&Yh[m * D_IN + h * 128 + p] = hv;
            }
        }
    }
}

// ---------------- policy head (fuses split-K sum + bias + relu) ------------
__global__ __launch_bounds__(256)
void head_kernel(const float* __restrict__ Zp, const float* __restrict__ b_yo,
                 const float* __restrict__ Wh, const float* __restrict__ bh,
                 float* __restrict__ out)
{
    __shared__ float Zs[4][NUNITS];
    __shared__ float Ws[64][NACT];
    const int tid = threadIdx.x;
    const int m0  = blockIdx.x * 4;
    const int n   = tid & 63;
    const int mi  = tid >> 6;

    {
        const int r  = tid >> 6;
        const int c4 = (tid & 63) * 4;
        float4 z0 = *(const float4*)&Zp[(size_t)(m0 + r) * NUNITS + c4];
        float4 z1 = *(const float4*)&Zp[(size_t)M_TOT * NUNITS + (size_t)(m0 + r) * NUNITS + c4];
        float4 by = *(const float4*)&b_yo[c4];
        float4 v;
        v.x = fmaxf(z0.x + z1.x + by.x, 0.f);
        v.y = fmaxf(z0.y + z1.y + by.y, 0.f);
        v.z = fmaxf(z0.z + z1.z + by.z, 0.f);
        v.w = fmaxf(z0.w + z1.w + by.w, 0.f);
        *(float4*)&Zs[r][c4] = v;
    }

    float acc = bh[n];
    for (int k0 = 0; k0 < NUNITS; k0 += 64) {
        __syncthreads();
#pragma unroll
        for (int j = 0; j < 4; j++) {
            int idx = tid + j * 256;
            int r = idx >> 4, c4 = (idx & 15) * 4;
            *(float4*)&Ws[r][c4] = *(const float4*)&Wh[(size_t)(k0 + r) * NACT + c4];
        }
        __syncthreads();
#pragma unroll
        for (int k = 0; k < 64; k++)
            acc = fmaf(Zs[mi][k0 + k], Ws[k][n], acc);
    }
    out[(size_t)(m0 + mi) * NACT + n] = acc;
}

// ---------------- launch (parallel segment scans + correction) --------------
extern "C" void kernel_launch(void* const* d_in, const int* in_sizes, int n_in,
                              void* d_out, int out_size)
{
    const float* obs     = (const float*)d_in[0];
    const float* W_in    = (const float*)d_in[1];
    const float* b_in    = (const float*)d_in[2];
    const float* A_log   = (const float*)d_in[3];
    const float* dt_bias = (const float*)d_in[4];
    const float* W_dt    = (const float*)d_in[5];
    const float* W_B     = (const float*)d_in[6];
    const float* W_C     = (const float*)d_in[7];
    const float* W_yo    = (const float*)d_in[8];
    const float* b_yo    = (const float*)d_in[9];
    const float* W_head  = (const float*)d_in[10];
    const float* b_head  = (const float*)d_in[11];
    float* out = (float*)d_out;

    float *X, *Bmp, *Cmp, *dts, *dec, *Zp;
    __half *Xh, *Yh, *Yu, *obsh, *obsl, *Winh, *WBh, *WCh, *Wyoh;
    ull* hst;
    cudaGetSymbolAddress((void**)&X,    g_X);
    cudaGetSymbolAddress((void**)&Xh,   g_Xh);
    cudaGetSymbolAddress((void**)&Bmp,  g_Bm);
    cudaGetSymbolAddress((void**)&Cmp,  g_Cm);
    cudaGetSymbolAddress((void**)&dts,  g_dt);
    cudaGetSymbolAddress((void**)&dec,  g_dec);
    cudaGetSymbolAddress((void**)&Yh,   g_Yh);
    cudaGetSymbolAddress((void**)&Yu,   g_Yu);
    cudaGetSymbolAddress((void**)&Zp,   g_Zp);
    cudaGetSymbolAddress((void**)&hst,  g_hstate);
    cudaGetSymbolAddress((void**)&obsh, g_obs_hi);
    cudaGetSymbolAddress((void**)&obsl, g_obs_lo);
    cudaGetSymbolAddress((void**)&Winh, g_Win_h);
    cudaGetSymbolAddress((void**)&WBh,  g_WB_h);
    cudaGetSymbolAddress((void**)&WCh,  g_WC_h);
    cudaGetSymbolAddress((void**)&Wyoh, g_Wyo_h);

    static cudaStream_t sB = nullptr, sC = nullptr;
    static cudaEvent_t eFork, eWB, eWC, eWyo, eWin, eX, eB1, eB2, eC1, eC2, eD, eS1, eS2;
    if (!sB) {
        cudaStreamCreateWithFlags(&sB, cudaStreamNonBlocking);
        cudaStreamCreateWithFlags(&sC, cudaStreamNonBlocking);
        cudaEvent_t* evs[13] = {&eFork, &eWB, &eWC, &eWyo, &eWin, &eX,
                                &eB1, &eB2, &eC1, &eC2, &eD, &eS1, &eS2};
        for (int i = 0; i < 13; i++)
            cudaEventCreateWithFlags(evs[i], cudaEventDisableTiming);
        cudaFuncSetAttribute(mma_gemm1h<8>,  cudaFuncAttributeMaxDynamicSharedMemorySize, SMEM_F16_3);
        cudaFuncSetAttribute(mma_gemm_h1<64>, cudaFuncAttributeMaxDynamicSharedMemorySize, SMEM_F16_2);
        cudaFuncSetAttribute(mma_gemm_h1<32>, cudaFuncAttributeMaxDynamicSharedMemorySize, SMEM_F16_2);
    }

    cudaEventRecord(eFork, 0);
    cudaStreamWaitEvent(sB, eFork, 0);
    cudaStreamWaitEvent(sC, eFork, 0);

    // side-stream weight conversions
    transconv_h_kernel<<<dim3(HN / 32, D_IN / 32), dim3(32, 8), 0, sB>>>(W_B, WBh, D_IN, HN);
    cudaEventRecord(eWB, sB);
    transconv_h_kernel<<<dim3(D_IN / 32, OBS_DIM / 32), dim3(32, 8), 0, sC>>>(W_in, Winh, OBS_DIM, D_IN);
    cudaEventRecord(eWin, sC);
    transconv_h_kernel<<<dim3(HN / 32, D_IN / 32), dim3(32, 8), 0, sC>>>(W_C, WCh, D_IN, HN);
    cudaEventRecord(eWC, sC);
    transconv_h_kernel<<<dim3(NUNITS / 32, D_IN / 32), dim3(32, 8), 0, sC>>>(W_yo, Wyoh, D_IN, NUNITS);
    cudaEventRecord(eWyo, sC);

    // main: obs conversion (fp16 hi/lo), GEMM1 (fp16 2-pass)
    rowconv_kernel<<<(M_TOT * OBS_DIM / 4 + 255) / 256, 256>>>(obs, obsh, obsl, M_TOT * OBS_DIM);
    cudaStreamWaitEvent(0, eWin, 0);
    mma_gemm1h<8><<<dim3(D_IN / 128, M_TOT / 128), 256, SMEM_F16_3>>>(
        obsh, obsl, Winh, b_in, X, Xh, M_TOT, D_IN, OBS_DIM);
    cudaEventRecord(eX, 0);

    const size_t hA = (size_t)M_HALF * D_IN;
    const size_t hB = (size_t)M_HALF * HN;

    // B projection halves on main stream
    cudaStreamWaitEvent(0, eWB, 0);
    mma_gemm_h1<64><<<dim3(HN / 128, M_HALF / 128, 1), 256, SMEM_F16_2>>>(
        Xh, WBh, Bmp, M_HALF, HN, D_IN, 0);
    cudaEventRecord(eB1, 0);
    mma_gemm_h1<64><<<dim3(HN / 128, M_HALF / 128, 1), 256, SMEM_F16_2>>>(
        Xh + hA, WBh, Bmp + hB, M_HALF, HN, D_IN, 0);
    cudaEventRecord(eB2, 0);

    // C projection halves on stream B
    cudaStreamWaitEvent(sB, eX, 0);
    cudaStreamWaitEvent(sB, eWC, 0);
    mma_gemm_h1<64><<<dim3(HN / 128, M_HALF / 128, 1), 256, SMEM_F16_2, sB>>>(
        Xh, WCh, Cmp, M_HALF, HN, D_IN, 0);
    cudaEventRecord(eC1, sB);
    mma_gemm_h1<64><<<dim3(HN / 128, M_HALF / 128, 1), 256, SMEM_F16_2, sB>>>(
        Xh + hA, WCh, Cmp + hB, M_HALF, HN, D_IN, 0);
    cudaEventRecord(eC2, sB);

    // dt/decay on stream C
    cudaStreamWaitEvent(sC, eX, 0);
    dtdecay_kernel<<<M_TOT / 16, 256, 0, sC>>>(X, W_dt, dt_bias, A_log, dts, dec);
    cudaEventRecord(eD, sC);

    // scan seg0 on sC (zero init, writes Yh, stores H_mid)
    cudaStreamWaitEvent(sC, eB1, 0);
    cudaStreamWaitEvent(sC, eC1, 0);
    scan_kernel<<<BSZ * NHEAD, 128, 0, sC>>>(X, Bmp, Cmp, dts, dec, Yh, nullptr,
                                             hst, 0, T_HALF, 1);
    cudaEventRecord(eS1, sC);

    // scan seg1 on sB (zero init, writes Yu fp16), CONCURRENT with seg0
    cudaStreamWaitEvent(sB, eB2, 0);
    cudaStreamWaitEvent(sB, eD, 0);
    scan_kernel<<<BSZ * NHEAD, 128, 0, sB>>>(X, Bmp, Cmp, dts, dec, nullptr, Yu,
                                             hst, T_HALF, T_LEN, 0);
    // correction on sB (needs H_mid from seg0)
    cudaStreamWaitEvent(sB, eS1, 0);
    corr_kernel<<<128, 256, 0, sB>>>(Cmp, dec, hst, Yu, Yh);
    cudaEventRecord(eS2, sB);

    // yo projection halves (1-pass fp16, split-K=2) on main
    const size_t zstride = (size_t)M_TOT * NUNITS;
    cudaStreamWaitEvent(0, eWyo, 0);
    cudaStreamWaitEvent(0, eS1, 0);
    mma_gemm_h1<32><<<dim3(NUNITS / 128, M_HALF / 128, 2), 256, SMEM_F16_2>>>(
        Yh, Wyoh, Zp, M_HALF, NUNITS, D_IN, zstride);
    cudaStreamWaitEvent(0, eS2, 0);
    mma_gemm_h1<32><<<dim3(NUNITS / 128, M_HALF / 128, 2), 256, SMEM_F16_2>>>(
        Yh + hA, Wyoh, Zp + (size_t)M_HALF * NUNITS, M_HALF, NUNITS, D_IN, zstride);

    head_kernel<<<M_TOT / 4, 256>>>(Zp, b_yo, W_head, b_head, out);
}

// round 17
// speedup vs baseline: 1.1713x; 1.0337x over previous
#include <cuda_runtime.h>
#include <cuda_pipeline.h>
#include <cuda_bf16.h>
#include <cuda_fp16.h>
#include <math.h>
#include <stdint.h>

// ---------------- problem dims ----------------
#define T_LEN   512
#define BSZ     8
#define M_TOT   (T_LEN * BSZ)      // 4096
#define M_HALF  (M_TOT / 2)        // 2048
#define T_HALF  (T_LEN / 2)        // 256
#define OBS_DIM 256
#define D_IN    2048
#define NHEAD   16
#define NSTATE  64
#define PHEAD   128
#define NUNITS  256
#define NACT    64
#define HN      (NHEAD * NSTATE)    // 1024
#define WSCALE  32.0f
#define WISCALE (1.0f / 32.0f)

// ---------------- scratch ----------------
__device__ float          g_X   [M_TOT * D_IN];
__device__ __half         g_Xh  [M_TOT * D_IN];
__device__ float          g_Bm  [M_TOT * HN];
__device__ float          g_Cm  [M_TOT * HN];
__device__ float          g_dt  [M_TOT * NHEAD];
__device__ float          g_dec [M_TOT * NHEAD];
__device__ __half         g_Yh  [M_TOT * D_IN];          // final fp16 Y
__device__ __half         g_Yu  [M_HALF * D_IN];         // seg1 uncorrected y (fp16)
__device__ float          g_Zp  [2 * M_TOT * NUNITS];
__device__ unsigned long long g_hstate[128 * 128 * 32];  // H_mid (packed f32x2)
__device__ __half         g_obs_hi[M_TOT * OBS_DIM];
__device__ __half         g_obs_lo[M_TOT * OBS_DIM];
__device__ __half         g_Win_h[D_IN * OBS_DIM];       // fp16 x32
__device__ __half         g_WB_h [HN * D_IN];
__device__ __half         g_WC_h [HN * D_IN];
__device__ __half         g_Wyo_h[NUNITS * D_IN];

// ---------------- helpers ----------------
__device__ __forceinline__ uint32_t smem_u32(const void* p) {
    uint32_t a;
    asm("{ .reg .u64 t; cvta.to.shared.u64 t, %1; cvt.u32.u64 %0, t; }" : "=r"(a) : "l"(p));
    return a;
}
__device__ __forceinline__ void ldsm_x4(uint32_t* r, uint32_t addr) {
    asm volatile("ldmatrix.sync.aligned.m8n8.x4.shared.b16 {%0,%1,%2,%3}, [%4];"
                 : "=r"(r[0]), "=r"(r[1]), "=r"(r[2]), "=r"(r[3]) : "r"(addr));
}
__device__ __forceinline__ void ldsm_x2(uint32_t* r, uint32_t addr) {
    asm volatile("ldmatrix.sync.aligned.m8n8.x2.shared.b16 {%0,%1}, [%2];"
                 : "=r"(r[0]), "=r"(r[1]) : "r"(addr));
}
__device__ __forceinline__ void mma_f16(float* c, const uint32_t* a, const uint32_t* b) {
    asm volatile("mma.sync.aligned.m16n8k16.row.col.f32.f16.f16.f32 "
                 "{%0,%1,%2,%3}, {%4,%5,%6,%7}, {%8,%9}, {%0,%1,%2,%3};"
                 : "+f"(c[0]), "+f"(c[1]), "+f"(c[2]), "+f"(c[3])
                 : "r"(a[0]), "r"(a[1]), "r"(a[2]), "r"(a[3]), "r"(b[0]), "r"(b[1]));
}
typedef unsigned long long ull;
__device__ __forceinline__ ull pk2(float lo, float hi) {
    ull r; asm("mov.b64 %0, {%1, %2};" : "=l"(r) : "f"(lo), "f"(hi)); return r;
}
__device__ __forceinline__ void upk2(float& lo, float& hi, ull v) {
    asm("mov.b64 {%0, %1}, %2;" : "=f"(lo), "=f"(hi) : "l"(v));
}
__device__ __forceinline__ ull fma2(ull a, ull b, ull c) {
    ull d; asm("fma.rn.f32x2 %0, %1, %2, %3;" : "=l"(d) : "l"(a), "l"(b), "l"(c)); return d;
}
__device__ __forceinline__ ull mul2(ull a, ull b) {
    ull d; asm("mul.rn.f32x2 %0, %1, %2;" : "=l"(d) : "l"(a), "l"(b)); return d;
}

// ---------------- conversion kernels ----------------
__global__ void rowconv_kernel(const float* __restrict__ src,
                               __half* __restrict__ hi,
                               __half* __restrict__ lo, int n)
{
    int i = blockIdx.x * blockDim.x + threadIdx.x;
    if (i * 4 >= n) return;
    float4 v = *(const float4*)(src + i * 4);
    float vv[4] = {v.x, v.y, v.z, v.w};
#pragma unroll
    for (int j = 0; j < 4; j++) {
        __half h = __float2half_rn(vv[j]);
        hi[i * 4 + j] = h;
        lo[i * 4 + j] = __float2half_rn(vv[j] - __half2float(h));
    }
}

__global__ void transconv_h_kernel(const float* __restrict__ W,
                                   __half* __restrict__ Th, int K, int N)
{
    __shared__ float s[32][33];
    int tx = threadIdx.x, ty = threadIdx.y;
    int n0 = blockIdx.x * 32, k0 = blockIdx.y * 32;
#pragma unroll
    for (int i = 0; i < 4; i++)
        s[ty + i * 8][tx] = W[(size_t)(k0 + ty + i * 8) * N + n0 + tx];
    __syncthreads();
#pragma unroll
    for (int i = 0; i < 4; i++) {
        int n = n0 + ty + i * 8, k = k0 + tx;
        Th[(size_t)n * K + k] = __float2half_rn(s[tx][ty + i * 8] * WSCALE);
    }
}

// ---------------- tile geometry ----------------
#define ROWB      80
#define TILE_B    (128 * ROWB)
#define BUF_B2    (2 * TILE_B)
#define SMEM_F16_2 (2 * BUF_B2)
#define BUF_B3    (3 * TILE_B)
#define SMEM_F16_3 (2 * BUF_B3)

// ---------------- fp16 2-pass GEMM1 (bias+relu, X fp32 + Xh fp16) ----------
template<int KCHUNKS>
__global__ __launch_bounds__(256, 2)
void mma_gemm1h(const __half* __restrict__ Ahi, const __half* __restrict__ Alo,
                const __half* __restrict__ Wm, const float* __restrict__ bias,
                float* __restrict__ Cout, __half* __restrict__ Ch,
                int M, int N, int K)
{
    extern __shared__ char smem[];
    const uint32_t sbase = smem_u32(smem);
    const int tid  = threadIdx.x;
    const int lane = tid & 31, wid = tid >> 5;
    const int warp_m = wid >> 2;
    const int warp_n = wid & 3;
    const int bn = blockIdx.x * 128;
    const int bm = blockIdx.y * 128;

    const __half* srcs[3] = {Ahi, Alo, Wm};

    auto load_chunk = [&](int c, int buf) {
#pragma unroll
        for (int w = 0; w < 3; w++) {
            const int rowbase = (w < 2) ? bm : bn;
            const __half* src = srcs[w];
#pragma unroll
            for (int t = 0; t < 2; t++) {
                int idx = tid + t * 256;
                int row = idx >> 2, seg = idx & 3;
                char* dst = smem + buf * BUF_B3 + w * TILE_B + row * ROWB + seg * 16;
                const char* s = (const char*)src +
                    ((size_t)(rowbase + row) * K + (size_t)c * 32) * 2 + seg * 16;
                __pipeline_memcpy_async(dst, s, 16);
            }
        }
    };

    float acc[4][4][4];
#pragma unroll
    for (int i = 0; i < 4; i++)
#pragma unroll
        for (int j = 0; j < 4; j++)
#pragma unroll
            for (int q = 0; q < 4; q++) acc[i][j][q] = 0.f;

    load_chunk(0, 0);
    __pipeline_commit();
    __pipeline_wait_prior(0);
    __syncthreads();

    const uint32_t a_lane_off = (uint32_t)((lane & 15) * ROWB + (lane >> 4) * 16);
    const uint32_t b_lane_off = (uint32_t)((lane & 7) * ROWB + ((lane >> 3) & 1) * 16);

    for (int c = 0; c < KCHUNKS; c++) {
        if (c + 1 < KCHUNKS) { load_chunk(c + 1, (c + 1) & 1); __pipeline_commit(); }
        const uint32_t bufb = sbase + (c & 1) * BUF_B3;
#pragma unroll
        for (int s = 0; s < 2; s++) {
            uint32_t ah[4][4], al[4][4];
            const uint32_t ks = s * 32;
#pragma unroll
            for (int i = 0; i < 4; i++) {
                uint32_t ro = (uint32_t)((warp_m * 64 + i * 16) * ROWB) + ks + a_lane_off;
                ldsm_x4(ah[i], bufb + 0 * TILE_B + ro);
                ldsm_x4(al[i], bufb + 1 * TILE_B + ro);
            }
#pragma unroll
            for (int j = 0; j < 4; j++) {
                uint32_t wf[2];
                uint32_t ro = (uint32_t)((warp_n * 32 + j * 8) * ROWB) + ks + b_lane_off;
                ldsm_x2(wf, bufb + 2 * TILE_B + ro);
#pragma unroll
                for (int i = 0; i < 4; i++) {
                    mma_f16(acc[i][j], ah[i], wf);
                    mma_f16(acc[i][j], al[i], wf);
                }
            }
        }
        if (c + 1 < KCHUNKS) __pipeline_wait_prior(0);
        __syncthreads();
    }

    const int r0 = lane >> 2;
    const int q0 = (lane & 3) * 2;
#pragma unroll
    for (int j = 0; j < 4; j++) {
        const int n0 = bn + warp_n * 32 + j * 8 + q0;
        float b0 = bias[n0], b1 = bias[n0 + 1];
#pragma unroll
        for (int i = 0; i < 4; i++) {
            const int m0 = bm + warp_m * 64 + i * 16 + r0;
            float v0 = fmaxf(acc[i][j][0] * WISCALE + b0, 0.f);
            float v1 = fmaxf(acc[i][j][1] * WISCALE + b1, 0.f);
            float v2 = fmaxf(acc[i][j][2] * WISCALE + b0, 0.f);
            float v3 = fmaxf(acc[i][j][3] * WISCALE + b1, 0.f);
            *(float2*)&Cout[(size_t)m0 * N + n0]       = make_float2(v0, v1);
            *(float2*)&Cout[(size_t)(m0 + 8) * N + n0] = make_float2(v2, v3);
            __half2 hp0 = {__float2half_rn(v0), __float2half_rn(v1)};
            __half2 hp1 = {__float2half_rn(v2), __float2half_rn(v3)};
            *(__half2*)&Ch[(size_t)m0 * N + n0]       = hp0;
            *(__half2*)&Ch[(size_t)(m0 + 8) * N + n0] = hp1;
        }
    }
}

// ---------------- fp16 single-pass GEMM (B, C, yo) -------------------------
template<int KCHUNKS>
__global__ __launch_bounds__(256, 2)
void mma_gemm_h1(const __half* __restrict__ A, const __half* __restrict__ Wm,
                 float* __restrict__ Cout, int M, int N, int K, size_t zstride)
{
    extern __shared__ char smem[];
    const uint32_t sbase = smem_u32(smem);
    const int tid  = threadIdx.x;
    const int lane = tid & 31, wid = tid >> 5;
    const int warp_m = wid >> 2;
    const int warp_n = wid & 3;
    const int bn = blockIdx.x * 128;
    const int bm = blockIdx.y * 128;
    const int zoff = blockIdx.z * KCHUNKS;
    Cout += (size_t)blockIdx.z * zstride;

    const __half* srcs[2] = {A, Wm};

    auto load_chunk = [&](int gc, int buf) {
#pragma unroll
        for (int w = 0; w < 2; w++) {
            const int rowbase = (w == 0) ? bm : bn;
            const __half* src = srcs[w];
#pragma unroll
            for (int t = 0; t < 2; t++) {
                int idx = tid + t * 256;
                int row = idx >> 2, seg = idx & 3;
                char* dst = smem + buf * BUF_B2 + w * TILE_B + row * ROWB + seg * 16;
                const char* s = (const char*)src +
                    ((size_t)(rowbase + row) * K + (size_t)gc * 32) * 2 + seg * 16;
                __pipeline_memcpy_async(dst, s, 16);
            }
        }
    };

    float acc[4][4][4];
#pragma unroll
    for (int i = 0; i < 4; i++)
#pragma unroll
        for (int j = 0; j < 4; j++)
#pragma unroll
            for (int q = 0; q < 4; q++) acc[i][j][q] = 0.f;

    load_chunk(zoff, 0);
    __pipeline_commit();
    __pipeline_wait_prior(0);
    __syncthreads();

    const uint32_t a_lane_off = (uint32_t)((lane & 15) * ROWB + (lane >> 4) * 16);
    const uint32_t b_lane_off = (uint32_t)((lane & 7) * ROWB + ((lane >> 3) & 1) * 16);

    for (int c = 0; c < KCHUNKS; c++) {
        if (c + 1 < KCHUNKS) { load_chunk(zoff + c + 1, (c + 1) & 1); __pipeline_commit(); }
        const uint32_t bufb = sbase + (c & 1) * BUF_B2;
#pragma unroll
        for (int s = 0; s < 2; s++) {
            uint32_t af[4][4];
            const uint32_t ks = s * 32;
#pragma unroll
            for (int i = 0; i < 4; i++) {
                uint32_t ro = (uint32_t)((warp_m * 64 + i * 16) * ROWB) + ks + a_lane_off;
                ldsm_x4(af[i], bufb + 0 * TILE_B + ro);
            }
#pragma unroll
            for (int j = 0; j < 4; j++) {
                uint32_t wf[2];
                uint32_t ro = (uint32_t)((warp_n * 32 + j * 8) * ROWB) + ks + b_lane_off;
                ldsm_x2(wf, bufb + 1 * TILE_B + ro);
#pragma unroll
                for (int i = 0; i < 4; i++)
                    mma_f16(acc[i][j], af[i], wf);
            }
        }
        if (c + 1 < KCHUNKS) __pipeline_wait_prior(0);
        __syncthreads();
    }

    const int r0 = lane >> 2;
    const int q0 = (lane & 3) * 2;
#pragma unroll
    for (int j = 0; j < 4; j++) {
        const int n0 = bn + warp_n * 32 + j * 8 + q0;
#pragma unroll
        for (int i = 0; i < 4; i++) {
            const int m0 = bm + warp_m * 64 + i * 16 + r0;
            *(float2*)&Cout[(size_t)m0 * N + n0] =
                make_float2(acc[i][j][0] * WISCALE, acc[i][j][1] * WISCALE);
            *(float2*)&Cout[(size_t)(m0 + 8) * N + n0] =
                make_float2(acc[i][j][2] * WISCALE, acc[i][j][3] * WISCALE);
        }
    }
}

// ---------------- dt projection + softplus + decay ----------------
__global__ __launch_bounds__(256)
void dtdecay_kernel(const float* __restrict__ X, const float* __restrict__ W_dt,
                    const float* __restrict__ dt_bias, const float* __restrict__ A_log,
                    float* __restrict__ dts, float* __restrict__ decs)
{
    __shared__ float Xs[16][64];
    __shared__ float Ws[64][16];
    const int tid = threadIdx.x;
    const int m0  = blockIdx.x * 16;
    const int h   = tid & 15;
    const int mi  = tid >> 4;

    float acc = 0.f;
    for (int k0 = 0; k0 < D_IN; k0 += 64) {
        __syncthreads();
        *(float4*)&Xs[tid >> 4][(tid & 15) * 4] =
            *(const float4*)&X[(size_t)(m0 + (tid >> 4)) * D_IN + k0 + (tid & 15) * 4];
        *(float4*)&Ws[tid >> 2][(tid & 3) * 4] =
            *(const float4*)&W_dt[(size_t)(k0 + (tid >> 2)) * NHEAD + (tid & 3) * 4];
        __syncthreads();
#pragma unroll
        for (int k = 0; k < 64; k++)
            acc = fmaf(Xs[mi][k], Ws[k][h], acc);
    }
    const int m = m0 + mi;
    float v  = acc + dt_bias[h];
    float dt = (v > 20.f) ? v : log1pf(expf(v));
    float A  = expf(A_log[h]);
    dts[m * NHEAD + h]  = dt;
    decs[m * NHEAD + h] = expf(-A * dt);
}

// ---------------- selective scan (16B vectorized staging) -------------------
__global__ __launch_bounds__(128, 1)
void scan_kernel(const float* __restrict__ X, const float* __restrict__ Bm,
                 const float* __restrict__ Cm, const float* __restrict__ dts,
                 const float* __restrict__ decs,
                 __half* __restrict__ Yh, __half* __restrict__ Yu,
                 ull* __restrict__ hstate, int t0, int t1, int store_state)
{
    const int bh = blockIdx.x;
    const int b  = bh >> 4;
    const int h  = bh & 15;
    const int tid = threadIdx.x;

    __shared__ __align__(16) float xb[4][4][PHEAD];
    __shared__ __align__(16) float Bb[4][4][NSTATE];
    __shared__ __align__(16) float Cb[4][4][NSTATE];
    __shared__ float sc[4][4][2];

    ull hs2[32];
#pragma unroll
    for (int i = 0; i < 32; i++) hs2[i] = 0ull;

    const int NP = (t1 - t0) >> 2;

    // 16B staging: per group of 4 steps, 256 16B transfers = 2 per thread.
    auto issue = [&](int g) {
        const int st = g & 3;
        const int base_t = t0 + 4 * g;
        {   // x: 128 transfers (u = tid>>5, chunk = tid&31)
            const int u = tid >> 5, ch = tid & 31;
            const size_t m = (size_t)(base_t + u) * BSZ + b;
            __pipeline_memcpy_async(&xb[st][u][ch * 4],
                                    X + m * D_IN + h * PHEAD + ch * 4, 16);
        }
        if (tid < 64) {   // B: 64 transfers (u = tid>>4, chunk = tid&15)
            const int u = tid >> 4, ch = tid & 15;
            const size_t m = (size_t)(base_t + u) * BSZ + b;
            __pipeline_memcpy_async(&Bb[st][u][ch * 4],
                                    Bm + m * HN + h * NSTATE + ch * 4, 16);
        } else {          // C: 64 transfers
            const int j = tid - 64;
            const int u = j >> 4, ch = j & 15;
            const size_t m = (size_t)(base_t + u) * BSZ + b;
            __pipeline_memcpy_async(&Cb[st][u][ch * 4],
                                    Cm + m * HN + h * NSTATE + ch * 4, 16);
        }
        if (tid < 8) {    // scalars: dt/dec for 4 steps
            const int u = tid >> 1, w = tid & 1;
            const float* src = w ? decs : dts;
            const size_t m = (size_t)(base_t + u) * BSZ + b;
            __pipeline_memcpy_async(&sc[st][u][w], src + m * NHEAD + h, 4);
        }
    };

    issue(0); __pipeline_commit();
    issue(1); __pipeline_commit();
    issue(2); __pipeline_commit();

    for (int g = 0; g < NP; g++) {
        const int st = g & 3;
        __pipeline_wait_prior(2);
        __syncthreads();
        if (g + 3 < NP) issue(g + 3);
        __pipeline_commit();

#pragma unroll
        for (int u = 0; u < 4; u++) {
            const float dtv = sc[st][u][0];
            const float dec = sc[st][u][1];
            const float cc  = dtv * xb[st][u][tid];
            const ull dec2 = pk2(dec, dec);
            const ull cc2  = pk2(cc, cc);

            const longlong2* B2 = (const longlong2*)Bb[st][u];
            const longlong2* C2 = (const longlong2*)Cb[st][u];
            ull ya = 0ull, yb = 0ull;
#pragma unroll
            for (int j = 0; j < 16; j++) {
                longlong2 bv = B2[j];
                longlong2 cv = C2[j];
                hs2[2*j]   = fma2(dec2, hs2[2*j],   mul2(cc2, (ull)bv.x));
                ya         = fma2(hs2[2*j],   (ull)cv.x, ya);
                hs2[2*j+1] = fma2(dec2, hs2[2*j+1], mul2(cc2, (ull)bv.y));
                yb         = fma2(hs2[2*j+1], (ull)cv.y, yb);
            }
            float a0, a1, c0, c1;
            upk2(a0, a1, ya);
            upk2(c0, c1, yb);
            const float y = (a0 + a1) + (c0 + c1);

            const int t = t0 + 4 * g + u;
            const size_t m = (size_t)t * BSZ + b;
            if (Yu)
                Yu[(m - (size_t)M_HALF) * D_IN + h * PHEAD + tid] = __float2half_rn(y);
            else
                Yh[m * D_IN + h * PHEAD + tid] = __float2half_rn(y);
        }
    }

    if (store_state) {
        ull* hptr = hstate + ((size_t)bh * 128 + tid) * 32;
#pragma unroll
        for (int i = 0; i < 32; i++) hptr[i] = hs2[i];
    }
}

// ---------------- segment correction: y += cumdec(t) * (C_t . H_mid[p,:]) ---
__global__ __launch_bounds__(256)
void corr_kernel(const float* __restrict__ Cm, const float* __restrict__ decs,
                 const ull* __restrict__ hstate, const __half* __restrict__ Yu,
                 __half* __restrict__ Yh)
{
    const int bh = blockIdx.x;
    const int b = bh >> 4, h = bh & 15;
    const int tid = threadIdx.x;
    const int lane = tid & 31, wid = tid >> 5;

    __shared__ __half H0s[128][72];
    __shared__ __half Cs[64][72];
    __shared__ float cd[256];

    const ull* hbase = hstate + (size_t)bh * 128 * 32;
#pragma unroll
    for (int i = 0; i < 16; i++) {
        int idx = tid * 16 + i;
        int p = idx >> 5, j = idx & 31;
        float f0, f1;
        upk2(f0, f1, hbase[(size_t)p * 32 + j]);
        H0s[p][2 * j]     = __float2half_rn(f0);
        H0s[p][2 * j + 1] = __float2half_rn(f1);
    }

    cd[tid] = decs[((size_t)(T_HALF + tid) * BSZ + b) * NHEAD + h];
    __syncthreads();
    for (int off = 1; off < 256; off <<= 1) {
        float v = cd[tid];
        float u = (tid >= off) ? cd[tid - off] : 1.f;
        __syncthreads();
        cd[tid] = v * u;
        __syncthreads();
    }

    const int warp_m = wid & 3;
    const int warp_n = wid >> 2;
    const uint32_t a_off = (uint32_t)((lane & 15) * 144 + (lane >> 4) * 16);
    const uint32_t b_off = (uint32_t)((lane & 7) * 144 + ((lane >> 3) & 1) * 16);
    const uint32_t cbase0 = smem_u32(&Cs[0][0]) + (uint32_t)(warp_m * 16) * 144 + a_off;
    const uint32_t hbase0 = smem_u32(&H0s[0][0]) + (uint32_t)(warp_n * 64) * 144 + b_off;
    const int r0 = lane >> 2, q0 = (lane & 3) * 2;

    for (int tt = 0; tt < 4; tt++) {
        __syncthreads();
#pragma unroll
        for (int i = 0; i < 16; i++) {
            int idx = tid * 16 + i;
            int j = idx >> 6, n = idx & 63;
            size_t m = (size_t)(T_HALF + tt * 64 + j) * BSZ + b;
            Cs[j][n] = __float2half_rn(Cm[m * HN + h * 64 + n]);
        }
        __syncthreads();

        float acc[8][4];
#pragma unroll
        for (int jg = 0; jg < 8; jg++)
#pragma unroll
            for (int q = 0; q < 4; q++) acc[jg][q] = 0.f;

#pragma unroll
        for (int ks = 0; ks < 4; ks++) {
            uint32_t af[4];
            ldsm_x4(af, cbase0 + ks * 32);
#pragma unroll
            for (int jg = 0; jg < 8; jg++) {
                uint32_t bf[2];
                ldsm_x2(bf, hbase0 + (uint32_t)(jg * 8) * 144 + ks * 32);
                mma_f16(acc[jg], af, bf);
            }
        }

#pragma unroll
        for (int jg = 0; jg < 8; jg++) {
            const int p = warp_n * 64 + jg * 8 + q0;
#pragma unroll
            for (int ii = 0; ii < 2; ii++) {
                const int tl = tt * 64 + warp_m * 16 + ii * 8 + r0;
                const size_t m = (size_t)(T_HALF + tl) * BSZ + b;
                const float c = cd[tl];
                const size_t uoff = (m - (size_t)M_HALF) * D_IN + h * 128 + p;
                __half2 uv = *(const __half2*)&Yu[uoff];
                float2 uf = __half22float2(uv);
                float y0 = uf.x + c * acc[jg][ii * 2];
                float y1 = uf.y + c * acc[jg][ii * 2 + 1];
                __half2 hv = {__float2half_rn(y0), __float2half_rn(y1)};
                *(__half2*)&Yh[m * D_IN + h * 128 + p] = hv;
            }
        }
    }
}

// ---------------- policy head (fuses split-K sum + bias + relu) ------------
__global__ __launch_bounds__(256)
void head_kernel(const float* __restrict__ Zp, const float* __restrict__ b_yo,
                 const float* __restrict__ Wh, const float* __restrict__ bh,
                 float* __restrict__ out)
{
    __shared__ float Zs[4][NUNITS];
    __shared__ float Ws[64][NACT];
    const int tid = threadIdx.x;
    const int m0  = blockIdx.x * 4;
    const int n   = tid & 63;
    const int mi  = tid >> 6;

    {
        const int r  = tid >> 6;
        const int c4 = (tid & 63) * 4;
        float4 z0 = *(const float4*)&Zp[(size_t)(m0 + r) * NUNITS + c4];
        float4 z1 = *(const float4*)&Zp[(size_t)M_TOT * NUNITS + (size_t)(m0 + r) * NUNITS + c4];
        float4 by = *(const float4*)&b_yo[c4];
        float4 v;
        v.x = fmaxf(z0.x + z1.x + by.x, 0.f);
        v.y = fmaxf(z0.y + z1.y + by.y, 0.f);
        v.z = fmaxf(z0.z + z1.z + by.z, 0.f);
        v.w = fmaxf(z0.w + z1.w + by.w, 0.f);
        *(float4*)&Zs[r][c4] = v;
    }

    float acc = bh[n];
    for (int k0 = 0; k0 < NUNITS; k0 += 64) {
        __syncthreads();
#pragma unroll
        for (int j = 0; j < 4; j++) {
            int idx = tid + j * 256;
            int r = idx >> 4, c4 = (idx & 15) * 4;
            *(float4*)&Ws[r][c4] = *(const float4*)&Wh[(size_t)(k0 + r) * NACT + c4];
        }
        __syncthreads();
#pragma unroll
        for (int k = 0; k < 64; k++)
            acc = fmaf(Zs[mi][k0 + k], Ws[k][n], acc);
    }
    out[(size_t)(m0 + mi) * NACT + n] = acc;
}

// ---------------- launch (parallel segment scans + correction) --------------
extern "C" void kernel_launch(void* const* d_in, const int* in_sizes, int n_in,
                              void* d_out, int out_size)
{
    const float* obs     = (const float*)d_in[0];
    const float* W_in    = (const float*)d_in[1];
    const float* b_in    = (const float*)d_in[2];
    const float* A_log   = (const float*)d_in[3];
    const float* dt_bias = (const float*)d_in[4];
    const float* W_dt    = (const float*)d_in[5];
    const float* W_B     = (const float*)d_in[6];
    const float* W_C     = (const float*)d_in[7];
    const float* W_yo    = (const float*)d_in[8];
    const float* b_yo    = (const float*)d_in[9];
    const float* W_head  = (const float*)d_in[10];
    const float* b_head  = (const float*)d_in[11];
    float* out = (float*)d_out;

    float *X, *Bmp, *Cmp, *dts, *dec, *Zp;
    __half *Xh, *Yh, *Yu, *obsh, *obsl, *Winh, *WBh, *WCh, *Wyoh;
    ull* hst;
    cudaGetSymbolAddress((void**)&X,    g_X);
    cudaGetSymbolAddress((void**)&Xh,   g_Xh);
    cudaGetSymbolAddress((void**)&Bmp,  g_Bm);
    cudaGetSymbolAddress((void**)&Cmp,  g_Cm);
    cudaGetSymbolAddress((void**)&dts,  g_dt);
    cudaGetSymbolAddress((void**)&dec,  g_dec);
    cudaGetSymbolAddress((void**)&Yh,   g_Yh);
    cudaGetSymbolAddress((void**)&Yu,   g_Yu);
    cudaGetSymbolAddress((void**)&Zp,   g_Zp);
    cudaGetSymbolAddress((void**)&hst,  g_hstate);
    cudaGetSymbolAddress((void**)&obsh, g_obs_hi);
    cudaGetSymbolAddress((void**)&obsl, g_obs_lo);
    cudaGetSymbolAddress((void**)&Winh, g_Win_h);
    cudaGetSymbolAddress((void**)&WBh,  g_WB_h);
    cudaGetSymbolAddress((void**)&WCh,  g_WC_h);
    cudaGetSymbolAddress((void**)&Wyoh, g_Wyo_h);

    static cudaStream_t sB = nullptr, sC = nullptr;
    static cudaEvent_t eFork, eWB, eWC, eWyo, eWin, eX, eB1, eB2, eC1, eC2, eD, eS1, eS2;
    if (!sB) {
        cudaStreamCreateWithFlags(&sB, cudaStreamNonBlocking);
        cudaStreamCreateWithFlags(&sC, cudaStreamNonBlocking);
        cudaEvent_t* evs[13] = {&eFork, &eWB, &eWC, &eWyo, &eWin, &eX,
                                &eB1, &eB2, &eC1, &eC2, &eD, &eS1, &eS2};
        for (int i = 0; i < 13; i++)
            cudaEventCreateWithFlags(evs[i], cudaEventDisableTiming);
        cudaFuncSetAttribute(mma_gemm1h<8>,  cudaFuncAttributeMaxDynamicSharedMemorySize, SMEM_F16_3);
        cudaFuncSetAttribute(mma_gemm_h1<64>, cudaFuncAttributeMaxDynamicSharedMemorySize, SMEM_F16_2);
        cudaFuncSetAttribute(mma_gemm_h1<32>, cudaFuncAttributeMaxDynamicSharedMemorySize, SMEM_F16_2);
    }

    cudaEventRecord(eFork, 0);
    cudaStreamWaitEvent(sB, eFork, 0);
    cudaStreamWaitEvent(sC, eFork, 0);

    // side-stream weight conversions
    transconv_h_kernel<<<dim3(HN / 32, D_IN / 32), dim3(32, 8), 0, sB>>>(W_B, WBh, D_IN, HN);
    cudaEventRecord(eWB, sB);
    transconv_h_kernel<<<dim3(D_IN / 32, OBS_DIM / 32), dim3(32, 8), 0, sC>>>(W_in, Winh, OBS_DIM, D_IN);
    cudaEventRecord(eWin, sC);
    transconv_h_kernel<<<dim3(HN / 32, D_IN / 32), dim3(32, 8), 0, sC>>>(W_C, WCh, D_IN, HN);
    cudaEventRecord(eWC, sC);
    transconv_h_kernel<<<dim3(NUNITS / 32, D_IN / 32), dim3(32, 8), 0, sC>>>(W_yo, Wyoh, D_IN, NUNITS);
    cudaEventRecord(eWyo, sC);

    // main: obs conversion (fp16 hi/lo), GEMM1 (fp16 2-pass)
    rowconv_kernel<<<(M_TOT * OBS_DIM / 4 + 255) / 256, 256>>>(obs, obsh, obsl, M_TOT * OBS_DIM);
    cudaStreamWaitEvent(0, eWin, 0);
    mma_gemm1h<8><<<dim3(D_IN / 128, M_TOT / 128), 256, SMEM_F16_3>>>(
        obsh, obsl, Winh, b_in, X, Xh, M_TOT, D_IN, OBS_DIM);
    cudaEventRecord(eX, 0);

    const size_t hA = (size_t)M_HALF * D_IN;
    const size_t hB = (size_t)M_HALF * HN;

    // B projection halves on main stream
    cudaStreamWaitEvent(0, eWB, 0);
    mma_gemm_h1<64><<<dim3(HN / 128, M_HALF / 128, 1), 256, SMEM_F16_2>>>(
        Xh, WBh, Bmp, M_HALF, HN, D_IN, 0);
    cudaEventRecord(eB1, 0);
    mma_gemm_h1<64><<<dim3(HN / 128, M_HALF / 128, 1), 256, SMEM_F16_2>>>(
        Xh + hA, WBh, Bmp + hB, M_HALF, HN, D_IN, 0);
    cudaEventRecord(eB2, 0);

    // C projection halves on stream B
    cudaStreamWaitEvent(sB, eX, 0);
    cudaStreamWaitEvent(sB, eWC, 0);
    mma_gemm_h1<64><<<dim3(HN / 128, M_HALF / 128, 1), 256, SMEM_F16_2, sB>>>(
        Xh, WCh, Cmp, M_HALF, HN, D_IN, 0);
    cudaEventRecord(eC1, sB);
    mma_gemm_h1<64><<<dim3(HN / 128, M_HALF / 128, 1), 256, SMEM_F16_2, sB>>>(
        Xh + hA, WCh, Cmp + hB, M_HALF, HN, D_IN, 0);
    cudaEventRecord(eC2, sB);

    // dt/decay on stream C
    cudaStreamWaitEvent(sC, eX, 0);
    dtdecay_kernel<<<M_TOT / 16, 256, 0, sC>>>(X, W_dt, dt_bias, A_log, dts, dec);
    cudaEventRecord(eD, sC);

    // scan seg0 on sC (zero init, writes Yh, stores H_mid)
    cudaStreamWaitEvent(sC, eB1, 0);
    cudaStreamWaitEvent(sC, eC1, 0);
    scan_kernel<<<BSZ * NHEAD, 128, 0, sC>>>(X, Bmp, Cmp, dts, dec, Yh, nullptr,
                                             hst, 0, T_HALF, 1);
    cudaEventRecord(eS1, sC);

    // scan seg1 on sB (zero init, writes Yu fp16), CONCURRENT with seg0
    cudaStreamWaitEvent(sB, eB2, 0);
    cudaStreamWaitEvent(sB, eD, 0);
    scan_kernel<<<BSZ * NHEAD, 128, 0, sB>>>(X, Bmp, Cmp, dts, dec, nullptr, Yu,
                                             hst, T_HALF, T_LEN, 0);
    // correction on sB (needs H_mid from seg0)
    cudaStreamWaitEvent(sB, eS1, 0);
    corr_kernel<<<128, 256, 0, sB>>>(Cmp, dec, hst, Yu, Yh);
    cudaEventRecord(eS2, sB);

    // yo projection halves (1-pass fp16, split-K=2) on main
    const size_t zstride = (size_t)M_TOT * NUNITS;
    cudaStreamWaitEvent(0, eWyo, 0);
    cudaStreamWaitEvent(0, eS1, 0);
    mma_gemm_h1<32><<<dim3(NUNITS / 128, M_HALF / 128, 2), 256, SMEM_F16_2>>>(
        Yh, Wyoh, Zp, M_HALF, NUNITS, D_IN, zstride);
    cudaStreamWaitEvent(0, eS2, 0);
    mma_gemm_h1<32><<<dim3(NUNITS / 128, M_HALF / 128, 2), 256, SMEM_F16_2>>>(
        Yh + hA, Wyoh, Zp + (size_t)M_HALF * NUNITS, M_HALF, NUNITS, D_IN, zstride);

    head_kernel<<<M_TOT / 4, 256>>>(Zp, b_yo, W_head, b_head, out);
}